// round 1
// baseline (speedup 1.0000x reference)
#include <cuda_runtime.h>
#include <math.h>

// sLSTM cell, fused: h = o * ((f*c_prev + i*z) / (f*n_prev + i))
// pre-activations from two K-phases: x@W_gᵀ (K=1024) then h_prev@R_gᵀ (K=2048).
//
// One kernel. Each CTA computes a 64x64 tile of h, holding 4 gate accumulators
// (z,i,f,o) per output element. The A tile (x / h_prev rows) is loaded to smem
// once per k-step and reused across all 4 gate weight tiles -> FFMA-bound.

namespace {

constexpr int BATCH = 4096;
constexpr int DIN   = 1024;
constexpr int DH    = 2048;

constexpr int BM = 64;   // batch rows per CTA
constexpr int BN = 64;   // hidden cols per CTA
constexpr int BK = 16;   // k per step
constexpr int PAD = 4;   // smem row padding (keeps float4 alignment, breaks conflicts)

struct Smem {
    float As[BK][BM + PAD];       // A transposed: [k][row]
    float Bs[4][BK][BN + PAD];    // per gate, transposed: [k][col]
};

__global__ __launch_bounds__(256, 2)
void slstm_fused_kernel(const float* __restrict__ x,
                        const float* __restrict__ h_prev,
                        const float* __restrict__ c_prev,
                        const float* __restrict__ n_prev,
                        const float* __restrict__ Wz, const float* __restrict__ Wi,
                        const float* __restrict__ Wf, const float* __restrict__ Wo,
                        const float* __restrict__ bz, const float* __restrict__ bi,
                        const float* __restrict__ bf, const float* __restrict__ bo,
                        const float* __restrict__ Rz, const float* __restrict__ Ri,
                        const float* __restrict__ Rf, const float* __restrict__ Ro,
                        float* __restrict__ h_out)
{
    __shared__ Smem s;

    const int t  = threadIdx.x;
    const int tx = t & 15;          // output-col group (4 cols each)
    const int ty = t >> 4;          // output-row group (4 rows each)
    const int row0 = blockIdx.y * BM;
    const int col0 = blockIdx.x * BN;

    // loader mapping: each thread loads one float4 (row = t>>2, k-quad = t&3)
    const int lr = t >> 2;          // 0..63
    const int lk = (t & 3) << 2;    // 0,4,8,12

    float acc[4][16];               // [gate][r*4+c]
    #pragma unroll
    for (int g = 0; g < 4; ++g)
        #pragma unroll
        for (int i = 0; i < 16; ++i) acc[g][i] = 0.0f;

    #pragma unroll 1
    for (int phase = 0; phase < 2; ++phase) {
        const float* A  = phase ? h_prev : x;
        const int    K  = phase ? DH : DIN;
        const float* B0 = phase ? Rz : Wz;
        const float* B1 = phase ? Ri : Wi;
        const float* B2 = phase ? Rf : Wf;
        const float* B3 = phase ? Ro : Wo;

        const float* aP  = A  + (size_t)(row0 + lr) * K + lk;
        const float* bP0 = B0 + (size_t)(col0 + lr) * K + lk;
        const float* bP1 = B1 + (size_t)(col0 + lr) * K + lk;
        const float* bP2 = B2 + (size_t)(col0 + lr) * K + lk;
        const float* bP3 = B3 + (size_t)(col0 + lr) * K + lk;

        #pragma unroll 1
        for (int k0 = 0; k0 < K; k0 += BK) {
            // stage tile in registers (overlaps with previous compute tail)
            const float4 av  = *(const float4*)(aP  + k0);
            const float4 bv0 = *(const float4*)(bP0 + k0);
            const float4 bv1 = *(const float4*)(bP1 + k0);
            const float4 bv2 = *(const float4*)(bP2 + k0);
            const float4 bv3 = *(const float4*)(bP3 + k0);

            __syncthreads();   // previous iteration's compute done reading smem

            s.As[lk + 0][lr] = av.x;  s.As[lk + 1][lr] = av.y;
            s.As[lk + 2][lr] = av.z;  s.As[lk + 3][lr] = av.w;
            s.Bs[0][lk + 0][lr] = bv0.x; s.Bs[0][lk + 1][lr] = bv0.y;
            s.Bs[0][lk + 2][lr] = bv0.z; s.Bs[0][lk + 3][lr] = bv0.w;
            s.Bs[1][lk + 0][lr] = bv1.x; s.Bs[1][lk + 1][lr] = bv1.y;
            s.Bs[1][lk + 2][lr] = bv1.z; s.Bs[1][lk + 3][lr] = bv1.w;
            s.Bs[2][lk + 0][lr] = bv2.x; s.Bs[2][lk + 1][lr] = bv2.y;
            s.Bs[2][lk + 2][lr] = bv2.z; s.Bs[2][lk + 3][lr] = bv2.w;
            s.Bs[3][lk + 0][lr] = bv3.x; s.Bs[3][lk + 1][lr] = bv3.y;
            s.Bs[3][lk + 2][lr] = bv3.z; s.Bs[3][lk + 3][lr] = bv3.w;

            __syncthreads();

            #pragma unroll
            for (int k = 0; k < BK; ++k) {
                const float4 a4 = *(const float4*)&s.As[k][ty << 2];
                const float ar[4] = {a4.x, a4.y, a4.z, a4.w};
                #pragma unroll
                for (int g = 0; g < 4; ++g) {
                    const float4 b4 = *(const float4*)&s.Bs[g][k][tx << 2];
                    const float bc[4] = {b4.x, b4.y, b4.z, b4.w};
                    #pragma unroll
                    for (int r = 0; r < 4; ++r)
                        #pragma unroll
                        for (int c = 0; c < 4; ++c)
                            acc[g][r * 4 + c] = fmaf(ar[r], bc[c], acc[g][r * 4 + c]);
                }
            }
        }
    }

    // ---- fused sLSTM epilogue ----
    const int cj = col0 + (tx << 2);
    const float4 bz4 = *(const float4*)(bz + cj);
    const float4 bi4 = *(const float4*)(bi + cj);
    const float4 bf4 = *(const float4*)(bf + cj);
    const float4 bo4 = *(const float4*)(bo + cj);
    const float bzr[4] = {bz4.x, bz4.y, bz4.z, bz4.w};
    const float bir[4] = {bi4.x, bi4.y, bi4.z, bi4.w};
    const float bfr[4] = {bf4.x, bf4.y, bf4.z, bf4.w};
    const float bor[4] = {bo4.x, bo4.y, bo4.z, bo4.w};

    #pragma unroll
    for (int r = 0; r < 4; ++r) {
        const int rb = row0 + (ty << 2) + r;
        const size_t base = (size_t)rb * DH + cj;
        const float4 c4 = *(const float4*)(c_prev + base);
        const float4 n4 = *(const float4*)(n_prev + base);
        const float cpr[4] = {c4.x, c4.y, c4.z, c4.w};
        const float npr[4] = {n4.x, n4.y, n4.z, n4.w};

        float hv[4];
        #pragma unroll
        for (int c = 0; c < 4; ++c) {
            const float az = acc[0][r * 4 + c] + bzr[c];
            const float ai = acc[1][r * 4 + c] + bir[c];
            const float af = acc[2][r * 4 + c] + bfr[c];
            const float ao = acc[3][r * 4 + c] + bor[c];
            const float z  = tanhf(az);
            const float iv = expf(ai);
            const float fv = expf(af);
            const float ov = 1.0f / (1.0f + expf(-ao));
            const float cn = fv * cpr[c] + iv * z;
            const float nn = fv * npr[c] + iv;
            hv[c] = ov * (cn / nn);
        }
        *(float4*)(h_out + base) = make_float4(hv[0], hv[1], hv[2], hv[3]);
    }
}

} // namespace

extern "C" void kernel_launch(void* const* d_in, const int* in_sizes, int n_in,
                              void* d_out, int out_size)
{
    const float* x      = (const float*)d_in[0];
    const float* h_prev = (const float*)d_in[1];
    const float* c_prev = (const float*)d_in[2];
    const float* n_prev = (const float*)d_in[3];
    const float* Wz = (const float*)d_in[4];
    const float* Wi = (const float*)d_in[5];
    const float* Wf = (const float*)d_in[6];
    const float* Wo = (const float*)d_in[7];
    const float* bz = (const float*)d_in[8];
    const float* bi = (const float*)d_in[9];
    const float* bf = (const float*)d_in[10];
    const float* bo = (const float*)d_in[11];
    const float* Rz = (const float*)d_in[12];
    const float* Ri = (const float*)d_in[13];
    const float* Rf = (const float*)d_in[14];
    const float* Ro = (const float*)d_in[15];
    float* out = (float*)d_out;

    dim3 grid(DH / BN, BATCH / BM);   // (32, 64)
    dim3 block(256);
    slstm_fused_kernel<<<grid, block>>>(x, h_prev, c_prev, n_prev,
                                        Wz, Wi, Wf, Wo, bz, bi, bf, bo,
                                        Rz, Ri, Rf, Ro, out);
}

// round 3
// speedup vs baseline: 2.9923x; 2.9923x over previous
#include <cuda_runtime.h>
#include <cuda_bf16.h>
#include <cstdint>
#include <math.h>

// sLSTM cell: bf16x3 split-precision GEMM via portable mma.sync (HMMA) + fused epilogue.
// pre[b, g*2048+n] = sum_k Acat[b,k]*Bg[n,k];  Acat=[x|h_prev] (K=3072), Bg=[Wg|Rg].
// fp32 -> bf16 hi/lo; pre = Ah*Bh + Ah*Bl + Al*Bh accumulated in fp32.

// ---------------- constants ----------------
namespace {
constexpr int BATCH = 4096;
constexpr int DH    = 2048;
constexpr int KTOT  = 3072;

constexpr int BM = 64;               // batch rows / CTA
constexpr int BN = 64;               // cols per gate / CTA
constexpr int BK = 64;               // k per stage (128B rows in bf16)
constexpr int NCH = KTOT / BK;       // 48 stages

constexpr int A_HALF = BM * BK * 2;              // 8192 B (one of hi/lo)
constexpr int B_HALF = BN * BK * 2;              // 8192 B per gate per half
constexpr int OFF_AHI = 0;
constexpr int OFF_ALO = A_HALF;                  // 8192
constexpr int OFF_BHI = 2 * A_HALF;              // 16384  (+ g*8192)
constexpr int OFF_BLO = OFF_BHI + 4 * B_HALF;    // 49152  (+ g*8192)
constexpr int STAGE   = OFF_BLO + 4 * B_HALF;    // 81920
constexpr int SMEM_REQ = 2 * STAGE;              // 163840

constexpr int PRE_LD = 68;                       // epilogue smem row stride (floats)
} // namespace

// ---------------- bf16 hi/lo scratch ----------------
__device__ __nv_bfloat16 g_Ahi[(size_t)BATCH * KTOT];
__device__ __nv_bfloat16 g_Alo[(size_t)BATCH * KTOT];
__device__ __nv_bfloat16 g_Bhi[(size_t)4 * DH * KTOT];
__device__ __nv_bfloat16 g_Blo[(size_t)4 * DH * KTOT];

// ---------------- small asm helpers (portable PTX only) ----------------
__device__ __forceinline__ uint32_t smem_u32(const void* p) {
    uint32_t a;
    asm("{ .reg .u64 t; cvta.to.shared.u64 t, %1; cvt.u32.u64 %0, t; }" : "=r"(a) : "l"(p));
    return a;
}

__device__ __forceinline__ void cp_async16(uint32_t dst, const void* src) {
    asm volatile("cp.async.cg.shared.global [%0], [%1], 16;" :: "r"(dst), "l"(src) : "memory");
}
#define CP_COMMIT()  asm volatile("cp.async.commit_group;" ::: "memory")
#define CP_WAIT(n)   asm volatile("cp.async.wait_group %0;" :: "n"(n) : "memory")

__device__ __forceinline__ void ldm_x4(uint32_t* r, uint32_t addr) {
    asm volatile("ldmatrix.sync.aligned.m8n8.x4.shared.b16 {%0,%1,%2,%3}, [%4];"
                 : "=r"(r[0]), "=r"(r[1]), "=r"(r[2]), "=r"(r[3]) : "r"(addr));
}

__device__ __forceinline__ void mma_bf16(float* d, const uint32_t* a, const uint32_t* b) {
    asm volatile("mma.sync.aligned.m16n8k16.row.col.f32.bf16.bf16.f32 "
                 "{%0,%1,%2,%3}, {%4,%5,%6,%7}, {%8,%9}, {%0,%1,%2,%3};"
                 : "+f"(d[0]), "+f"(d[1]), "+f"(d[2]), "+f"(d[3])
                 : "r"(a[0]), "r"(a[1]), "r"(a[2]), "r"(a[3]), "r"(b[0]), "r"(b[1]));
}

#define SW128(off) ((off) ^ (((off) >> 3) & 0x70))

// ---------------- prepass: fp32 -> (hi, lo) bf16 ----------------
__global__ void __launch_bounds__(256)
cvt_kernel(const float* __restrict__ src,
           __nv_bfloat16* __restrict__ dhi, __nv_bfloat16* __restrict__ dlo,
           int kq_bits, long long dst_off)
{
    int i = blockIdx.x * blockDim.x + threadIdx.x;   // one float4 per thread
    int row = i >> kq_bits;
    int kq  = i & ((1 << kq_bits) - 1);
    const float4 v = reinterpret_cast<const float4*>(src)[i];
    long long o = dst_off + (long long)row * KTOT + (long long)kq * 4;

    float vs[4] = {v.x, v.y, v.z, v.w};
    __nv_bfloat16 h[4], l[4];
#pragma unroll
    for (int e = 0; e < 4; ++e) {
        h[e] = __float2bfloat16(vs[e]);
        l[e] = __float2bfloat16(vs[e] - __bfloat162float(h[e]));
    }
    *reinterpret_cast<__nv_bfloat162*>(dhi + o)     = __nv_bfloat162(h[0], h[1]);
    *reinterpret_cast<__nv_bfloat162*>(dhi + o + 2) = __nv_bfloat162(h[2], h[3]);
    *reinterpret_cast<__nv_bfloat162*>(dlo + o)     = __nv_bfloat162(l[0], l[1]);
    *reinterpret_cast<__nv_bfloat162*>(dlo + o + 2) = __nv_bfloat162(l[2], l[3]);
}

// ---------------- fused GEMM (HMMA) + sLSTM epilogue ----------------
__global__ void __launch_bounds__(256, 1)
slstm_hmma_kernel(const __nv_bfloat16* __restrict__ Ahi, const __nv_bfloat16* __restrict__ Alo,
                  const __nv_bfloat16* __restrict__ Bhi, const __nv_bfloat16* __restrict__ Blo,
                  const float* __restrict__ c_prev, const float* __restrict__ n_prev,
                  const float* __restrict__ bz, const float* __restrict__ bi,
                  const float* __restrict__ bf, const float* __restrict__ bo,
                  float* __restrict__ h_out)
{
    extern __shared__ char smem[];
    const uint32_t sbase = smem_u32(smem);

    const int tid  = threadIdx.x;
    const int lane = tid & 31;
    const int wid  = tid >> 5;           // 0..7
    const int gate = wid & 3;
    const int m0   = (wid >> 2) * 32;    // warp row offset (0 or 32)

    const int row0 = blockIdx.y * BM;
    const int col0 = blockIdx.x * BN;

    // ---- stage loader: 20 cp.async(16B) per thread ----
    const int lr = tid >> 3;             // 0..31  (row within a 64-row tile, x2 iters)
    const int ls = tid & 7;              // 16B segment within 128B row
    const uint32_t soff0 = SW128((uint32_t)(lr * 128 + ls * 16));
    const uint32_t soff1 = SW128((uint32_t)((lr + 32) * 128 + ls * 16));

    auto load_stage = [&](int s, int k0) {
        const uint32_t st = sbase + s * STAGE;
        const size_t a0 = (size_t)(row0 + lr) * KTOT + k0 + ls * 8;
        const size_t a1 = a0 + (size_t)32 * KTOT;
        cp_async16(st + OFF_AHI + soff0, Ahi + a0);
        cp_async16(st + OFF_AHI + soff1, Ahi + a1);
        cp_async16(st + OFF_ALO + soff0, Alo + a0);
        cp_async16(st + OFF_ALO + soff1, Alo + a1);
#pragma unroll
        for (int g = 0; g < 4; ++g) {
            const size_t b0 = (size_t)(g * DH + col0 + lr) * KTOT + k0 + ls * 8;
            const size_t b1 = b0 + (size_t)32 * KTOT;
            const uint32_t dh0 = st + OFF_BHI + g * B_HALF;
            const uint32_t dl0 = st + OFF_BLO + g * B_HALF;
            cp_async16(dh0 + soff0, Bhi + b0);
            cp_async16(dh0 + soff1, Bhi + b1);
            cp_async16(dl0 + soff0, Blo + b0);
            cp_async16(dl0 + soff1, Blo + b1);
        }
        CP_COMMIT();
    };

    // ---- per-lane ldmatrix address components ----
    const uint32_t xr     = (uint32_t)(lane & 7) << 4;          // swizzle XOR
    const uint32_t a_row  = (uint32_t)(lane & 15);              // + m0 + mt*16
    const uint32_t a_sel  = (lane & 16) ? 16u : 0u;
    const uint32_t b_rowl = (uint32_t)((lane & 7) + ((lane & 16) ? 8 : 0));
    const uint32_t b_sel  = (lane & 8) ? 16u : 0u;

    float acc[2][8][4];
#pragma unroll
    for (int mt = 0; mt < 2; ++mt)
#pragma unroll
        for (int nt = 0; nt < 8; ++nt)
#pragma unroll
            for (int e = 0; e < 4; ++e) acc[mt][nt][e] = 0.0f;

    load_stage(0, 0);

#pragma unroll 1
    for (int c = 0; c < NCH; ++c) {
        if (c + 1 < NCH) { load_stage((c + 1) & 1, (c + 1) * BK); CP_WAIT(1); }
        else             { CP_WAIT(0); }
        __syncthreads();

        const uint32_t st   = sbase + (c & 1) * STAGE;
        const uint32_t ahiB = st + OFF_AHI;
        const uint32_t aloB = st + OFF_ALO;
        const uint32_t bhiB = st + OFF_BHI + gate * B_HALF;
        const uint32_t bloB = st + OFF_BLO + gate * B_HALF;

#pragma unroll
        for (int j = 0; j < 4; ++j) {                    // k16 steps within BK=64
            const uint32_t akb = ((uint32_t)(j * 32) + a_sel) ^ xr;
            const uint32_t bkb = ((uint32_t)(j * 32) + b_sel) ^ xr;

            uint32_t ah[2][4], al[2][4];
#pragma unroll
            for (int mt = 0; mt < 2; ++mt) {
                const uint32_t rbyte = (m0 + mt * 16 + a_row) * 128;
                ldm_x4(ah[mt], ahiB + rbyte + akb);
                ldm_x4(al[mt], aloB + rbyte + akb);
            }
            uint32_t bh[4][4], bl[4][4];
#pragma unroll
            for (int np = 0; np < 4; ++np) {
                const uint32_t rbyte = (np * 16 + b_rowl) * 128;
                ldm_x4(bh[np], bhiB + rbyte + bkb);
                ldm_x4(bl[np], bloB + rbyte + bkb);
            }
#pragma unroll
            for (int mt = 0; mt < 2; ++mt)
#pragma unroll
                for (int np = 0; np < 4; ++np)
#pragma unroll
                    for (int s = 0; s < 2; ++s) {
                        float* d = acc[mt][np * 2 + s];
                        mma_bf16(d, ah[mt], &bh[np][2 * s]);
                        mma_bf16(d, ah[mt], &bl[np][2 * s]);
                        mma_bf16(d, al[mt], &bh[np][2 * s]);
                    }
        }
        __syncthreads();   // done reading buf (c&1) before it is overwritten
    }

    // ---- exchange gates through smem, then fused sLSTM epilogue ----
    float* pre = reinterpret_cast<float*>(smem);   // [4][64][PRE_LD]
    float* pg = pre + (size_t)gate * 64 * PRE_LD;
#pragma unroll
    for (int mt = 0; mt < 2; ++mt) {
        const int r = m0 + mt * 16 + (lane >> 2);
#pragma unroll
        for (int nt = 0; nt < 8; ++nt) {
            const int cc = nt * 8 + (lane & 3) * 2;
            pg[(size_t)r * PRE_LD + cc]           = acc[mt][nt][0];
            pg[(size_t)r * PRE_LD + cc + 1]       = acc[mt][nt][1];
            pg[(size_t)(r + 8) * PRE_LD + cc]     = acc[mt][nt][2];
            pg[(size_t)(r + 8) * PRE_LD + cc + 1] = acc[mt][nt][3];
        }
    }
    __syncthreads();

    {
        const int r     = tid >> 2;            // 0..63
        const int cbase = (tid & 3) * 16;      // 16 cols per thread
        const size_t gbase = (size_t)(row0 + r) * DH + col0 + cbase;
        const int    col   = col0 + cbase;

#pragma unroll
        for (int q = 0; q < 4; ++q) {
            const int cq = cbase + q * 4;
            const float4 bz4 = *reinterpret_cast<const float4*>(bz + col + q * 4);
            const float4 bi4 = *reinterpret_cast<const float4*>(bi + col + q * 4);
            const float4 bf4 = *reinterpret_cast<const float4*>(bf + col + q * 4);
            const float4 bo4 = *reinterpret_cast<const float4*>(bo + col + q * 4);
            const float4 c4  = *reinterpret_cast<const float4*>(c_prev + gbase + q * 4);
            const float4 n4  = *reinterpret_cast<const float4*>(n_prev + gbase + q * 4);
            const float bzr[4] = {bz4.x, bz4.y, bz4.z, bz4.w};
            const float bir[4] = {bi4.x, bi4.y, bi4.z, bi4.w};
            const float bfr[4] = {bf4.x, bf4.y, bf4.z, bf4.w};
            const float bor[4] = {bo4.x, bo4.y, bo4.z, bo4.w};
            const float cpr[4] = {c4.x, c4.y, c4.z, c4.w};
            const float npr[4] = {n4.x, n4.y, n4.z, n4.w};
            float hv[4];
#pragma unroll
            for (int e = 0; e < 4; ++e) {
                const size_t pix = (size_t)r * PRE_LD + cq + e;
                const float az = pre[0 * 64 * PRE_LD + pix] + bzr[e];
                const float ai = pre[1 * 64 * PRE_LD + pix] + bir[e];
                const float af = pre[2 * 64 * PRE_LD + pix] + bfr[e];
                const float ao = pre[3 * 64 * PRE_LD + pix] + bor[e];
                const float z  = tanhf(az);
                const float iv = expf(ai);
                const float fv = expf(af);
                const float ov = 1.0f / (1.0f + expf(-ao));
                const float cn = fv * cpr[e] + iv * z;
                const float nn = fv * npr[e] + iv;
                hv[e] = ov * (cn / nn);
            }
            *reinterpret_cast<float4*>(h_out + gbase + q * 4) =
                make_float4(hv[0], hv[1], hv[2], hv[3]);
        }
    }
}

// ---------------- launch ----------------
extern "C" void kernel_launch(void* const* d_in, const int* in_sizes, int n_in,
                              void* d_out, int out_size)
{
    const float* x      = (const float*)d_in[0];
    const float* h_prev = (const float*)d_in[1];
    const float* c_prev = (const float*)d_in[2];
    const float* n_prev = (const float*)d_in[3];
    const float* W[4] = {(const float*)d_in[4], (const float*)d_in[5],
                         (const float*)d_in[6], (const float*)d_in[7]};
    const float* bz = (const float*)d_in[8];
    const float* bi = (const float*)d_in[9];
    const float* bf = (const float*)d_in[10];
    const float* bo = (const float*)d_in[11];
    const float* R[4] = {(const float*)d_in[12], (const float*)d_in[13],
                         (const float*)d_in[14], (const float*)d_in[15]};
    float* out = (float*)d_out;

    __nv_bfloat16 *pAhi, *pAlo, *pBhi, *pBlo;
    cudaGetSymbolAddress((void**)&pAhi, g_Ahi);
    cudaGetSymbolAddress((void**)&pAlo, g_Alo);
    cudaGetSymbolAddress((void**)&pBhi, g_Bhi);
    cudaGetSymbolAddress((void**)&pBlo, g_Blo);

    cvt_kernel<<<(BATCH * 1024 / 4) / 256, 256>>>(x, pAhi, pAlo, 8, 0);
    cvt_kernel<<<(BATCH * 2048 / 4) / 256, 256>>>(h_prev, pAhi, pAlo, 9, 1024);
    for (int g = 0; g < 4; ++g) {
        const long long gb = (long long)g * DH * KTOT;
        cvt_kernel<<<(DH * 1024 / 4) / 256, 256>>>(W[g], pBhi, pBlo, 8, gb);
        cvt_kernel<<<(DH * 2048 / 4) / 256, 256>>>(R[g], pBhi, pBlo, 9, gb + 1024);
    }

    cudaFuncSetAttribute(slstm_hmma_kernel, cudaFuncAttributeMaxDynamicSharedMemorySize, SMEM_REQ);
    dim3 grid(DH / BN, BATCH / BM);   // (32, 64)
    slstm_hmma_kernel<<<grid, 256, SMEM_REQ>>>(pAhi, pAlo, pBhi, pBlo,
                                               c_prev, n_prev, bz, bi, bf, bo, out);
}

// round 4
// speedup vs baseline: 3.1517x; 1.0533x over previous
#include <cuda_runtime.h>
#include <cuda_bf16.h>
#include <cstdint>
#include <math.h>

// sLSTM cell: bf16x3 split-precision GEMM via portable mma.sync (HMMA) + fused epilogue.
// R4: BM=128 (halves L2 traffic per output), wave-friendly grid order.

namespace {
constexpr int BATCH = 4096;
constexpr int DH    = 2048;
constexpr int KTOT  = 3072;

constexpr int BM = 128;              // batch rows / CTA
constexpr int BN = 64;               // cols per gate / CTA
constexpr int BK = 64;               // k per stage (128B rows in bf16)
constexpr int NCH = KTOT / BK;       // 48 stages

constexpr int A_HALF = BM * BK * 2;              // 16384 B
constexpr int B_HALF = BN * BK * 2;              // 8192 B per gate per half
constexpr int OFF_AHI = 0;
constexpr int OFF_ALO = A_HALF;                  // 16384
constexpr int OFF_BHI = 2 * A_HALF;              // 32768 (+ g*8192)
constexpr int OFF_BLO = OFF_BHI + 4 * B_HALF;    // 65536 (+ g*8192)
constexpr int STAGE   = OFF_BLO + 4 * B_HALF;    // 98304
constexpr int SMEM_REQ = 2 * STAGE;              // 196608

constexpr int PRE_LD = 68;                       // epilogue smem row stride (floats)
} // namespace

__device__ __nv_bfloat16 g_Ahi[(size_t)BATCH * KTOT];
__device__ __nv_bfloat16 g_Alo[(size_t)BATCH * KTOT];
__device__ __nv_bfloat16 g_Bhi[(size_t)4 * DH * KTOT];
__device__ __nv_bfloat16 g_Blo[(size_t)4 * DH * KTOT];

__device__ __forceinline__ uint32_t smem_u32(const void* p) {
    uint32_t a;
    asm("{ .reg .u64 t; cvta.to.shared.u64 t, %1; cvt.u32.u64 %0, t; }" : "=r"(a) : "l"(p));
    return a;
}
__device__ __forceinline__ void cp_async16(uint32_t dst, const void* src) {
    asm volatile("cp.async.cg.shared.global [%0], [%1], 16;" :: "r"(dst), "l"(src) : "memory");
}
#define CP_COMMIT()  asm volatile("cp.async.commit_group;" ::: "memory")
#define CP_WAIT(n)   asm volatile("cp.async.wait_group %0;" :: "n"(n) : "memory")

__device__ __forceinline__ void ldm_x4(uint32_t* r, uint32_t addr) {
    asm volatile("ldmatrix.sync.aligned.m8n8.x4.shared.b16 {%0,%1,%2,%3}, [%4];"
                 : "=r"(r[0]), "=r"(r[1]), "=r"(r[2]), "=r"(r[3]) : "r"(addr));
}
__device__ __forceinline__ void mma_bf16(float* d, const uint32_t* a, const uint32_t* b) {
    asm volatile("mma.sync.aligned.m16n8k16.row.col.f32.bf16.bf16.f32 "
                 "{%0,%1,%2,%3}, {%4,%5,%6,%7}, {%8,%9}, {%0,%1,%2,%3};"
                 : "+f"(d[0]), "+f"(d[1]), "+f"(d[2]), "+f"(d[3])
                 : "r"(a[0]), "r"(a[1]), "r"(a[2]), "r"(a[3]), "r"(b[0]), "r"(b[1]));
}
#define SW128(off) ((off) ^ (((off) >> 3) & 0x70))

// ---------------- prepass: fp32 -> (hi, lo) bf16 ----------------
__global__ void __launch_bounds__(256)
cvt_kernel(const float* __restrict__ src,
           __nv_bfloat16* __restrict__ dhi, __nv_bfloat16* __restrict__ dlo,
           int kq_bits, long long dst_off)
{
    int i = blockIdx.x * blockDim.x + threadIdx.x;
    int row = i >> kq_bits;
    int kq  = i & ((1 << kq_bits) - 1);
    const float4 v = reinterpret_cast<const float4*>(src)[i];
    long long o = dst_off + (long long)row * KTOT + (long long)kq * 4;

    float vs[4] = {v.x, v.y, v.z, v.w};
    __nv_bfloat16 h[4], l[4];
#pragma unroll
    for (int e = 0; e < 4; ++e) {
        h[e] = __float2bfloat16(vs[e]);
        l[e] = __float2bfloat16(vs[e] - __bfloat162float(h[e]));
    }
    *reinterpret_cast<__nv_bfloat162*>(dhi + o)     = __nv_bfloat162(h[0], h[1]);
    *reinterpret_cast<__nv_bfloat162*>(dhi + o + 2) = __nv_bfloat162(h[2], h[3]);
    *reinterpret_cast<__nv_bfloat162*>(dlo + o)     = __nv_bfloat162(l[0], l[1]);
    *reinterpret_cast<__nv_bfloat162*>(dlo + o + 2) = __nv_bfloat162(l[2], l[3]);
}

// ---------------- fused GEMM (HMMA) + sLSTM epilogue ----------------
__global__ void __launch_bounds__(256, 1)
slstm_hmma_kernel(const __nv_bfloat16* __restrict__ Ahi, const __nv_bfloat16* __restrict__ Alo,
                  const __nv_bfloat16* __restrict__ Bhi, const __nv_bfloat16* __restrict__ Blo,
                  const float* __restrict__ c_prev, const float* __restrict__ n_prev,
                  const float* __restrict__ bz, const float* __restrict__ bi,
                  const float* __restrict__ bf, const float* __restrict__ bo,
                  float* __restrict__ h_out)
{
    extern __shared__ char smem[];
    const uint32_t sbase = smem_u32(smem);

    const int tid  = threadIdx.x;
    const int lane = tid & 31;
    const int wid  = tid >> 5;           // 0..7
    const int gate = wid & 3;
    const int m0   = (wid >> 2) * 64;    // warp m-half: rows [m0, m0+64)

    // grid: x = row-block (fast -> wave covers all rows, few cols), y = col-block
    const int row0 = blockIdx.x * BM;
    const int col0 = blockIdx.y * BN;

    // ---- stage loader: 24 cp.async(16B) per thread ----
    const int lr = tid >> 3;             // 0..31
    const int ls = tid & 7;              // 16B segment in 128B row

    auto load_stage = [&](int s, int k0) {
        const uint32_t st = sbase + s * STAGE;
#pragma unroll
        for (int it = 0; it < 4; ++it) {             // A: 128 rows
            const int r = lr + it * 32;
            const uint32_t off = SW128((uint32_t)(r * 128 + ls * 16));
            const size_t gi = (size_t)(row0 + r) * KTOT + k0 + ls * 8;
            cp_async16(st + OFF_AHI + off, Ahi + gi);
            cp_async16(st + OFF_ALO + off, Alo + gi);
        }
#pragma unroll
        for (int g = 0; g < 4; ++g) {                // B: 64 rows per gate per half
#pragma unroll
            for (int it = 0; it < 2; ++it) {
                const int r = lr + it * 32;
                const uint32_t off = SW128((uint32_t)(r * 128 + ls * 16));
                const size_t gi = (size_t)(g * DH + col0 + r) * KTOT + k0 + ls * 8;
                cp_async16(st + OFF_BHI + g * B_HALF + off, Bhi + gi);
                cp_async16(st + OFF_BLO + g * B_HALF + off, Blo + gi);
            }
        }
        CP_COMMIT();
    };

    // ---- per-lane ldmatrix address components (validated in R3) ----
    const uint32_t xr     = (uint32_t)(lane & 7) << 4;
    const uint32_t a_row  = (uint32_t)(lane & 15);
    const uint32_t a_sel  = (lane & 16) ? 16u : 0u;
    const uint32_t b_rowl = (uint32_t)((lane & 7) + ((lane & 16) ? 8 : 0));
    const uint32_t b_sel  = (lane & 8) ? 16u : 0u;

    float acc[4][8][4];
#pragma unroll
    for (int mt = 0; mt < 4; ++mt)
#pragma unroll
        for (int nt = 0; nt < 8; ++nt)
#pragma unroll
            for (int e = 0; e < 4; ++e) acc[mt][nt][e] = 0.0f;

    load_stage(0, 0);

#pragma unroll 1
    for (int c = 0; c < NCH; ++c) {
        if (c + 1 < NCH) { load_stage((c + 1) & 1, (c + 1) * BK); CP_WAIT(1); }
        else             { CP_WAIT(0); }
        __syncthreads();

        const uint32_t st   = sbase + (c & 1) * STAGE;
        const uint32_t ahiB = st + OFF_AHI;
        const uint32_t aloB = st + OFF_ALO;
        const uint32_t bhiB = st + OFF_BHI + gate * B_HALF;
        const uint32_t bloB = st + OFF_BLO + gate * B_HALF;

#pragma unroll
        for (int j = 0; j < 4; ++j) {                // k16 steps within BK=64
            const uint32_t akb = ((uint32_t)(j * 32) + a_sel) ^ xr;
            const uint32_t bkb = ((uint32_t)(j * 32) + b_sel) ^ xr;

            uint32_t bh[4][4], bl[4][4];
#pragma unroll
            for (int np = 0; np < 4; ++np) {
                const uint32_t rbyte = (np * 16 + b_rowl) * 128;
                ldm_x4(bh[np], bhiB + rbyte + bkb);
                ldm_x4(bl[np], bloB + rbyte + bkb);
            }
#pragma unroll
            for (int mt = 0; mt < 4; ++mt) {
                uint32_t ah[4], al[4];
                const uint32_t rbyte = (m0 + mt * 16 + a_row) * 128;
                ldm_x4(ah, ahiB + rbyte + akb);
                ldm_x4(al, aloB + rbyte + akb);
#pragma unroll
                for (int np = 0; np < 4; ++np)
#pragma unroll
                    for (int s = 0; s < 2; ++s) {
                        float* d = acc[mt][np * 2 + s];
                        mma_bf16(d, ah, &bh[np][2 * s]);
                        mma_bf16(d, ah, &bl[np][2 * s]);
                        mma_bf16(d, al, &bh[np][2 * s]);
                    }
            }
        }
        __syncthreads();
    }

    // ---- exchange gates through smem, then fused sLSTM epilogue ----
    float* pre = reinterpret_cast<float*>(smem);   // [4][128][PRE_LD]
    float* pg = pre + (size_t)gate * BM * PRE_LD;
#pragma unroll
    for (int mt = 0; mt < 4; ++mt) {
        const int r = m0 + mt * 16 + (lane >> 2);
#pragma unroll
        for (int nt = 0; nt < 8; ++nt) {
            const int cc = nt * 8 + (lane & 3) * 2;
            pg[(size_t)r * PRE_LD + cc]           = acc[mt][nt][0];
            pg[(size_t)r * PRE_LD + cc + 1]       = acc[mt][nt][1];
            pg[(size_t)(r + 8) * PRE_LD + cc]     = acc[mt][nt][2];
            pg[(size_t)(r + 8) * PRE_LD + cc + 1] = acc[mt][nt][3];
        }
    }
    __syncthreads();

    {
        const int r     = tid >> 1;            // 0..127
        const int cbase = (tid & 1) * 32;      // 32 cols per thread
        const size_t gbase = (size_t)(row0 + r) * DH + col0 + cbase;
        const int    col   = col0 + cbase;

#pragma unroll
        for (int q = 0; q < 8; ++q) {
            const int cq = cbase + q * 4;
            const float4 bz4 = *reinterpret_cast<const float4*>(bz + col + q * 4);
            const float4 bi4 = *reinterpret_cast<const float4*>(bi + col + q * 4);
            const float4 bf4 = *reinterpret_cast<const float4*>(bf + col + q * 4);
            const float4 bo4 = *reinterpret_cast<const float4*>(bo + col + q * 4);
            const float4 c4  = *reinterpret_cast<const float4*>(c_prev + gbase + q * 4);
            const float4 n4  = *reinterpret_cast<const float4*>(n_prev + gbase + q * 4);
            const float bzr[4] = {bz4.x, bz4.y, bz4.z, bz4.w};
            const float bir[4] = {bi4.x, bi4.y, bi4.z, bi4.w};
            const float bfr[4] = {bf4.x, bf4.y, bf4.z, bf4.w};
            const float bor[4] = {bo4.x, bo4.y, bo4.z, bo4.w};
            const float cpr[4] = {c4.x, c4.y, c4.z, c4.w};
            const float npr[4] = {n4.x, n4.y, n4.z, n4.w};
            float hv[4];
#pragma unroll
            for (int e = 0; e < 4; ++e) {
                const size_t pix = (size_t)r * PRE_LD + cq + e;
                const float az = pre[0 * BM * PRE_LD + pix] + bzr[e];
                const float ai = pre[1 * BM * PRE_LD + pix] + bir[e];
                const float af = pre[2 * BM * PRE_LD + pix] + bfr[e];
                const float ao = pre[3 * BM * PRE_LD + pix] + bor[e];
                const float z  = tanhf(az);
                const float iv = expf(ai);
                const float fv = expf(af);
                const float ov = 1.0f / (1.0f + expf(-ao));
                const float cn = fv * cpr[e] + iv * z;
                const float nn = fv * npr[e] + iv;
                hv[e] = ov * (cn / nn);
            }
            *reinterpret_cast<float4*>(h_out + gbase + q * 4) =
                make_float4(hv[0], hv[1], hv[2], hv[3]);
        }
    }
}

// ---------------- launch ----------------
extern "C" void kernel_launch(void* const* d_in, const int* in_sizes, int n_in,
                              void* d_out, int out_size)
{
    const float* x      = (const float*)d_in[0];
    const float* h_prev = (const float*)d_in[1];
    const float* c_prev = (const float*)d_in[2];
    const float* n_prev = (const float*)d_in[3];
    const float* W[4] = {(const float*)d_in[4], (const float*)d_in[5],
                         (const float*)d_in[6], (const float*)d_in[7]};
    const float* bz = (const float*)d_in[8];
    const float* bi = (const float*)d_in[9];
    const float* bf = (const float*)d_in[10];
    const float* bo = (const float*)d_in[11];
    const float* R[4] = {(const float*)d_in[12], (const float*)d_in[13],
                         (const float*)d_in[14], (const float*)d_in[15]};
    float* out = (float*)d_out;

    __nv_bfloat16 *pAhi, *pAlo, *pBhi, *pBlo;
    cudaGetSymbolAddress((void**)&pAhi, g_Ahi);
    cudaGetSymbolAddress((void**)&pAlo, g_Alo);
    cudaGetSymbolAddress((void**)&pBhi, g_Bhi);
    cudaGetSymbolAddress((void**)&pBlo, g_Blo);

    cvt_kernel<<<(BATCH * 1024 / 4) / 256, 256>>>(x, pAhi, pAlo, 8, 0);
    cvt_kernel<<<(BATCH * 2048 / 4) / 256, 256>>>(h_prev, pAhi, pAlo, 9, 1024);
    for (int g = 0; g < 4; ++g) {
        const long long gb = (long long)g * DH * KTOT;
        cvt_kernel<<<(DH * 1024 / 4) / 256, 256>>>(W[g], pBhi, pBlo, 8, gb);
        cvt_kernel<<<(DH * 2048 / 4) / 256, 256>>>(R[g], pBhi, pBlo, 9, gb + 1024);
    }

    cudaFuncSetAttribute(slstm_hmma_kernel, cudaFuncAttributeMaxDynamicSharedMemorySize, SMEM_REQ);
    dim3 grid(BATCH / BM, DH / BN);   // (32 row-blocks fast, 32 col-blocks)
    slstm_hmma_kernel<<<grid, 256, SMEM_REQ>>>(pAhi, pAlo, pBhi, pBlo,
                                               c_prev, n_prev, bz, bi, bf, bo, out);
}

// round 5
// speedup vs baseline: 4.0226x; 1.2763x over previous
#include <cuda_runtime.h>
#include <cuda_fp16.h>
#include <cstdint>
#include <math.h>

// sLSTM cell: fp16x2 split GEMM via mma.sync (HMMA) + fused epilogue.
// pre[b, g*2048+n] = sum_k Acat[b,k]*Bg[n,k];  Acat=[x|h_prev] (K=3072), Bg=[Wg|Rg].
// A split fp16 hi/lo (exact to 2^-23); B rounded fp16 once (err ~2^-12 RMS -> ~1.4e-4).
// pre = Ah*B + Al*B, fp32 accumulate. 2 MMAs per k16 (was 3 with bf16x3).

namespace {
constexpr int BATCH = 4096;
constexpr int DH    = 2048;
constexpr int KTOT  = 3072;

constexpr int BM = 128;
constexpr int BN = 64;               // cols per gate
constexpr int BK = 64;               // 128B rows in fp16
constexpr int NCH = KTOT / BK;       // 48

constexpr int A_HALF = BM * BK * 2;              // 16384 B (hi or lo)
constexpr int B_TILE = BN * BK * 2;              // 8192 B per gate
constexpr int OFF_AHI = 0;
constexpr int OFF_ALO = A_HALF;                  // 16384
constexpr int OFF_B   = 2 * A_HALF;              // 32768 (+ g*8192)
constexpr int STAGE   = OFF_B + 4 * B_TILE;      // 65536
constexpr int PRE_LD  = 68;
constexpr int SMEM_REQ = (4 * BM * PRE_LD * 4 > 2 * STAGE) ? 4 * BM * PRE_LD * 4 : 2 * STAGE; // 139264
} // namespace

__device__ __half g_Ahi[(size_t)BATCH * KTOT];
__device__ __half g_Alo[(size_t)BATCH * KTOT];
__device__ __half g_B  [(size_t)4 * DH * KTOT];

__device__ __forceinline__ uint32_t smem_u32(const void* p) {
    uint32_t a;
    asm("{ .reg .u64 t; cvta.to.shared.u64 t, %1; cvt.u32.u64 %0, t; }" : "=r"(a) : "l"(p));
    return a;
}
__device__ __forceinline__ void cp_async16(uint32_t dst, const void* src) {
    asm volatile("cp.async.cg.shared.global [%0], [%1], 16;" :: "r"(dst), "l"(src) : "memory");
}
#define CP_COMMIT()  asm volatile("cp.async.commit_group;" ::: "memory")
#define CP_WAIT(n)   asm volatile("cp.async.wait_group %0;" :: "n"(n) : "memory")

__device__ __forceinline__ void ldm_x4(uint32_t* r, uint32_t addr) {
    asm volatile("ldmatrix.sync.aligned.m8n8.x4.shared.b16 {%0,%1,%2,%3}, [%4];"
                 : "=r"(r[0]), "=r"(r[1]), "=r"(r[2]), "=r"(r[3]) : "r"(addr));
}
__device__ __forceinline__ void mma_f16(float* d, const uint32_t* a, const uint32_t* b) {
    asm volatile("mma.sync.aligned.m16n8k16.row.col.f32.f16.f16.f32 "
                 "{%0,%1,%2,%3}, {%4,%5,%6,%7}, {%8,%9}, {%0,%1,%2,%3};"
                 : "+f"(d[0]), "+f"(d[1]), "+f"(d[2]), "+f"(d[3])
                 : "r"(a[0]), "r"(a[1]), "r"(a[2]), "r"(a[3]), "r"(b[0]), "r"(b[1]));
}
#define SW128(off) ((off) ^ (((off) >> 3) & 0x70))

// ---------------- prepass ----------------
__global__ void __launch_bounds__(256)
cvt_split(const float* __restrict__ src, __half* __restrict__ dhi, __half* __restrict__ dlo,
          int kq_bits, long long dst_off)
{
    int i = blockIdx.x * blockDim.x + threadIdx.x;
    int row = i >> kq_bits;
    int kq  = i & ((1 << kq_bits) - 1);
    const float4 v = reinterpret_cast<const float4*>(src)[i];
    long long o = dst_off + (long long)row * KTOT + (long long)kq * 4;
    float vs[4] = {v.x, v.y, v.z, v.w};
    __half h[4], l[4];
#pragma unroll
    for (int e = 0; e < 4; ++e) {
        h[e] = __float2half_rn(vs[e]);
        l[e] = __float2half_rn(vs[e] - __half2float(h[e]));
    }
    *reinterpret_cast<__half2*>(dhi + o)     = __half2(h[0], h[1]);
    *reinterpret_cast<__half2*>(dhi + o + 2) = __half2(h[2], h[3]);
    *reinterpret_cast<__half2*>(dlo + o)     = __half2(l[0], l[1]);
    *reinterpret_cast<__half2*>(dlo + o + 2) = __half2(l[2], l[3]);
}

__global__ void __launch_bounds__(256)
cvt_round(const float* __restrict__ src, __half* __restrict__ dst,
          int kq_bits, long long dst_off)
{
    int i = blockIdx.x * blockDim.x + threadIdx.x;
    int row = i >> kq_bits;
    int kq  = i & ((1 << kq_bits) - 1);
    const float4 v = reinterpret_cast<const float4*>(src)[i];
    long long o = dst_off + (long long)row * KTOT + (long long)kq * 4;
    *reinterpret_cast<__half2*>(dst + o)     = __half2(__float2half_rn(v.x), __float2half_rn(v.y));
    *reinterpret_cast<__half2*>(dst + o + 2) = __half2(__float2half_rn(v.z), __float2half_rn(v.w));
}

// ---------------- fused GEMM (HMMA) + sLSTM epilogue ----------------
__global__ void __launch_bounds__(512, 1)
slstm_hmma_kernel(const __half* __restrict__ Ahi, const __half* __restrict__ Alo,
                  const __half* __restrict__ B,
                  const float* __restrict__ c_prev, const float* __restrict__ n_prev,
                  const float* __restrict__ bz, const float* __restrict__ bi,
                  const float* __restrict__ bf, const float* __restrict__ bo,
                  float* __restrict__ h_out)
{
    extern __shared__ char smem[];
    const uint32_t sbase = smem_u32(smem);

    const int tid  = threadIdx.x;
    const int lane = tid & 31;
    const int wid  = tid >> 5;           // 0..15
    const int gate = wid & 3;
    const int m0   = (wid >> 2) * 32;    // warp rows [m0, m0+32)

    const int row0 = blockIdx.x * BM;    // row-block fast
    const int col0 = blockIdx.y * BN;

    // ---- stage loader: 8 cp.async(16B) per thread (512 threads, 64 KB stage) ----
    const int lr = tid >> 3;             // 0..63
    const int ls = tid & 7;

    auto load_stage = [&](int s, int k0) {
        const uint32_t st = sbase + s * STAGE;
#pragma unroll
        for (int it = 0; it < 2; ++it) {             // A: 128 rows, hi+lo
            const int r = lr + it * 64;
            const uint32_t off = SW128((uint32_t)(r * 128 + ls * 16));
            const size_t gi = (size_t)(row0 + r) * KTOT + k0 + ls * 8;
            cp_async16(st + OFF_AHI + off, Ahi + gi);
            cp_async16(st + OFF_ALO + off, Alo + gi);
        }
        {
            const uint32_t off = SW128((uint32_t)(lr * 128 + ls * 16));
#pragma unroll
            for (int g = 0; g < 4; ++g) {            // B: 64 rows per gate
                const size_t gi = (size_t)(g * DH + col0 + lr) * KTOT + k0 + ls * 8;
                cp_async16(st + OFF_B + g * B_TILE + off, B + gi);
            }
        }
        CP_COMMIT();
    };

    // ---- per-lane ldmatrix address components (validated R3/R4) ----
    const uint32_t xr     = (uint32_t)(lane & 7) << 4;
    const uint32_t a_row  = (uint32_t)(lane & 15);
    const uint32_t a_sel  = (lane & 16) ? 16u : 0u;
    const uint32_t b_rowl = (uint32_t)((lane & 7) + ((lane & 16) ? 8 : 0));
    const uint32_t b_sel  = (lane & 8) ? 16u : 0u;

    float acc[2][8][4];
#pragma unroll
    for (int mt = 0; mt < 2; ++mt)
#pragma unroll
        for (int nt = 0; nt < 8; ++nt)
#pragma unroll
            for (int e = 0; e < 4; ++e) acc[mt][nt][e] = 0.0f;

    load_stage(0, 0);

#pragma unroll 1
    for (int c = 0; c < NCH; ++c) {
        if (c + 1 < NCH) { load_stage((c + 1) & 1, (c + 1) * BK); CP_WAIT(1); }
        else             { CP_WAIT(0); }
        __syncthreads();

        const uint32_t st   = sbase + (c & 1) * STAGE;
        const uint32_t ahiB = st + OFF_AHI;
        const uint32_t aloB = st + OFF_ALO;
        const uint32_t bB   = st + OFF_B + gate * B_TILE;

#pragma unroll
        for (int j = 0; j < 4; ++j) {                // k16 steps within BK=64
            const uint32_t akb = ((uint32_t)(j * 32) + a_sel) ^ xr;
            const uint32_t bkb = ((uint32_t)(j * 32) + b_sel) ^ xr;

            uint32_t bh[4][4];
#pragma unroll
            for (int np = 0; np < 4; ++np) {
                const uint32_t rbyte = (np * 16 + b_rowl) * 128;
                ldm_x4(bh[np], bB + rbyte + bkb);
            }
#pragma unroll
            for (int mt = 0; mt < 2; ++mt) {
                uint32_t ah[4], al[4];
                const uint32_t rbyte = (m0 + mt * 16 + a_row) * 128;
                ldm_x4(ah, ahiB + rbyte + akb);
                ldm_x4(al, aloB + rbyte + akb);
#pragma unroll
                for (int np = 0; np < 4; ++np)
#pragma unroll
                    for (int s = 0; s < 2; ++s) {
                        float* d = acc[mt][np * 2 + s];
                        mma_f16(d, ah, &bh[np][2 * s]);
                        mma_f16(d, al, &bh[np][2 * s]);
                    }
            }
        }
        __syncthreads();
    }

    // ---- exchange gates through smem, then fused sLSTM epilogue ----
    float* pre = reinterpret_cast<float*>(smem);   // [4][128][PRE_LD]
    float* pg = pre + (size_t)gate * BM * PRE_LD;
#pragma unroll
    for (int mt = 0; mt < 2; ++mt) {
        const int r = m0 + mt * 16 + (lane >> 2);
#pragma unroll
        for (int nt = 0; nt < 8; ++nt) {
            const int cc = nt * 8 + (lane & 3) * 2;
            pg[(size_t)r * PRE_LD + cc]           = acc[mt][nt][0];
            pg[(size_t)r * PRE_LD + cc + 1]       = acc[mt][nt][1];
            pg[(size_t)(r + 8) * PRE_LD + cc]     = acc[mt][nt][2];
            pg[(size_t)(r + 8) * PRE_LD + cc + 1] = acc[mt][nt][3];
        }
    }
    __syncthreads();

    {
        const int r     = tid >> 2;            // 0..127
        const int cbase = (tid & 3) * 16;      // 16 cols per thread
        const size_t gbase = (size_t)(row0 + r) * DH + col0 + cbase;
        const int    col   = col0 + cbase;

#pragma unroll
        for (int q = 0; q < 4; ++q) {
            const int cq = cbase + q * 4;
            const float4 bz4 = *reinterpret_cast<const float4*>(bz + col + q * 4);
            const float4 bi4 = *reinterpret_cast<const float4*>(bi + col + q * 4);
            const float4 bf4 = *reinterpret_cast<const float4*>(bf + col + q * 4);
            const float4 bo4 = *reinterpret_cast<const float4*>(bo + col + q * 4);
            const float4 c4  = *reinterpret_cast<const float4*>(c_prev + gbase + q * 4);
            const float4 n4  = *reinterpret_cast<const float4*>(n_prev + gbase + q * 4);
            const float bzr[4] = {bz4.x, bz4.y, bz4.z, bz4.w};
            const float bir[4] = {bi4.x, bi4.y, bi4.z, bi4.w};
            const float bfr[4] = {bf4.x, bf4.y, bf4.z, bf4.w};
            const float bor[4] = {bo4.x, bo4.y, bo4.z, bo4.w};
            const float cpr[4] = {c4.x, c4.y, c4.z, c4.w};
            const float npr[4] = {n4.x, n4.y, n4.z, n4.w};
            float hv[4];
#pragma unroll
            for (int e = 0; e < 4; ++e) {
                const size_t pix = (size_t)r * PRE_LD + cq + e;
                const float az = pre[0 * BM * PRE_LD + pix] + bzr[e];
                const float ai = pre[1 * BM * PRE_LD + pix] + bir[e];
                const float af = pre[2 * BM * PRE_LD + pix] + bfr[e];
                const float ao = pre[3 * BM * PRE_LD + pix] + bor[e];
                const float z  = tanhf(az);
                const float iv = expf(ai);
                const float fv = expf(af);
                const float ov = 1.0f / (1.0f + expf(-ao));
                const float cn = fv * cpr[e] + iv * z;
                const float nn = fv * npr[e] + iv;
                hv[e] = ov * (cn / nn);
            }
            *reinterpret_cast<float4*>(h_out + gbase + q * 4) =
                make_float4(hv[0], hv[1], hv[2], hv[3]);
        }
    }
}

// ---------------- launch ----------------
extern "C" void kernel_launch(void* const* d_in, const int* in_sizes, int n_in,
                              void* d_out, int out_size)
{
    const float* x      = (const float*)d_in[0];
    const float* h_prev = (const float*)d_in[1];
    const float* c_prev = (const float*)d_in[2];
    const float* n_prev = (const float*)d_in[3];
    const float* W[4] = {(const float*)d_in[4], (const float*)d_in[5],
                         (const float*)d_in[6], (const float*)d_in[7]};
    const float* bz = (const float*)d_in[8];
    const float* bi = (const float*)d_in[9];
    const float* bf = (const float*)d_in[10];
    const float* bo = (const float*)d_in[11];
    const float* R[4] = {(const float*)d_in[12], (const float*)d_in[13],
                         (const float*)d_in[14], (const float*)d_in[15]};
    float* out = (float*)d_out;

    __half *pAhi, *pAlo, *pB;
    cudaGetSymbolAddress((void**)&pAhi, g_Ahi);
    cudaGetSymbolAddress((void**)&pAlo, g_Alo);
    cudaGetSymbolAddress((void**)&pB,   g_B);

    cvt_split<<<(BATCH * 1024 / 4) / 256, 256>>>(x, pAhi, pAlo, 8, 0);
    cvt_split<<<(BATCH * 2048 / 4) / 256, 256>>>(h_prev, pAhi, pAlo, 9, 1024);
    for (int g = 0; g < 4; ++g) {
        const long long gb = (long long)g * DH * KTOT;
        cvt_round<<<(DH * 1024 / 4) / 256, 256>>>(W[g], pB, 8, gb);
        cvt_round<<<(DH * 2048 / 4) / 256, 256>>>(R[g], pB, 9, gb + 1024);
    }

    cudaFuncSetAttribute(slstm_hmma_kernel, cudaFuncAttributeMaxDynamicSharedMemorySize, SMEM_REQ);
    dim3 grid(BATCH / BM, DH / BN);   // (32, 32)
    slstm_hmma_kernel<<<grid, 512, SMEM_REQ>>>(pAhi, pAlo, pB,
                                               c_prev, n_prev, bz, bi, bf, bo, out);
}

// round 6
// speedup vs baseline: 4.7872x; 1.1901x over previous
#include <cuda_runtime.h>
#include <cuda_fp16.h>
#include <cstdint>
#include <math.h>

// sLSTM cell: fp16x2 split GEMM via mma.sync (HMMA) + fused epilogue.
// R6: BM=64 w/ 256 threads -> 2 CTAs/SM (barrier overlap); prepass fused to 2 launches.

namespace {
constexpr int BATCH = 4096;
constexpr int DH    = 2048;
constexpr int KTOT  = 3072;

constexpr int BM = 64;
constexpr int BN = 64;               // cols per gate
constexpr int BK = 64;               // 128B rows in fp16
constexpr int NCH = KTOT / BK;       // 48

constexpr int A_HALF = BM * BK * 2;              // 8192 B (hi or lo)
constexpr int B_TILE = BN * BK * 2;              // 8192 B per gate
constexpr int OFF_AHI = 0;
constexpr int OFF_ALO = A_HALF;                  // 8192
constexpr int OFF_B   = 2 * A_HALF;              // 16384 (+ g*8192)
constexpr int STAGE   = OFF_B + 4 * B_TILE;      // 49152
constexpr int PRE_LD  = 68;
constexpr int SMEM_REQ = 2 * STAGE;              // 98304 (>= 4*64*68*4 = 69632)
} // namespace

__device__ __half g_Ahi[(size_t)BATCH * KTOT];
__device__ __half g_Alo[(size_t)BATCH * KTOT];
__device__ __half g_B  [(size_t)4 * DH * KTOT];

__device__ __forceinline__ uint32_t smem_u32(const void* p) {
    uint32_t a;
    asm("{ .reg .u64 t; cvta.to.shared.u64 t, %1; cvt.u32.u64 %0, t; }" : "=r"(a) : "l"(p));
    return a;
}
__device__ __forceinline__ void cp_async16(uint32_t dst, const void* src) {
    asm volatile("cp.async.cg.shared.global [%0], [%1], 16;" :: "r"(dst), "l"(src) : "memory");
}
#define CP_COMMIT()  asm volatile("cp.async.commit_group;" ::: "memory")
#define CP_WAIT(n)   asm volatile("cp.async.wait_group %0;" :: "n"(n) : "memory")

__device__ __forceinline__ void ldm_x4(uint32_t* r, uint32_t addr) {
    asm volatile("ldmatrix.sync.aligned.m8n8.x4.shared.b16 {%0,%1,%2,%3}, [%4];"
                 : "=r"(r[0]), "=r"(r[1]), "=r"(r[2]), "=r"(r[3]) : "r"(addr));
}
__device__ __forceinline__ void mma_f16(float* d, const uint32_t* a, const uint32_t* b) {
    asm volatile("mma.sync.aligned.m16n8k16.row.col.f32.f16.f16.f32 "
                 "{%0,%1,%2,%3}, {%4,%5,%6,%7}, {%8,%9}, {%0,%1,%2,%3};"
                 : "+f"(d[0]), "+f"(d[1]), "+f"(d[2]), "+f"(d[3])
                 : "r"(a[0]), "r"(a[1]), "r"(a[2]), "r"(a[3]), "r"(b[0]), "r"(b[1]));
}
#define SW128(off) ((off) ^ (((off) >> 3) & 0x70))

// ---------------- prepass A: x|h_prev -> fp16 hi/lo, fused (one launch) ----------------
// i indexes float4 over the [4096, 3072] concatenated A; kq<256 -> x, else h_prev.
__global__ void __launch_bounds__(256)
cvtA_kernel(const float* __restrict__ x, const float* __restrict__ h_prev,
            __half* __restrict__ dhi, __half* __restrict__ dlo)
{
    const int i   = blockIdx.x * blockDim.x + threadIdx.x;   // 0 .. 4096*768-1
    const int row = i / 768;
    const int kq  = i - row * 768;
    const float4 v = (kq < 256)
        ? reinterpret_cast<const float4*>(x)[row * 256 + kq]
        : reinterpret_cast<const float4*>(h_prev)[row * 512 + (kq - 256)];
    const long long o = (long long)row * KTOT + (long long)kq * 4;
    float vs[4] = {v.x, v.y, v.z, v.w};
    __half h[4], l[4];
#pragma unroll
    for (int e = 0; e < 4; ++e) {
        h[e] = __float2half_rn(vs[e]);
        l[e] = __float2half_rn(vs[e] - __half2float(h[e]));
    }
    *reinterpret_cast<__half2*>(dhi + o)     = __half2(h[0], h[1]);
    *reinterpret_cast<__half2*>(dhi + o + 2) = __half2(h[2], h[3]);
    *reinterpret_cast<__half2*>(dlo + o)     = __half2(l[0], l[1]);
    *reinterpret_cast<__half2*>(dlo + o + 2) = __half2(l[2], l[3]);
}

// ---------------- prepass B: all 4 gates W|R -> fp16, fused (one launch) ----------------
__global__ void __launch_bounds__(256)
cvtB_kernel(const float* __restrict__ W0, const float* __restrict__ W1,
            const float* __restrict__ W2, const float* __restrict__ W3,
            const float* __restrict__ R0, const float* __restrict__ R1,
            const float* __restrict__ R2, const float* __restrict__ R3,
            __half* __restrict__ dst)
{
    const int i    = blockIdx.x * blockDim.x + threadIdx.x;  // 0 .. 4*2048*768-1
    const int gate = i / (DH * 768);
    const int j    = i - gate * (DH * 768);
    const int row  = j / 768;
    const int kq   = j - row * 768;
    const float* W = (gate < 2) ? (gate == 0 ? W0 : W1) : (gate == 2 ? W2 : W3);
    const float* R = (gate < 2) ? (gate == 0 ? R0 : R1) : (gate == 2 ? R2 : R3);
    const float4 v = (kq < 256)
        ? reinterpret_cast<const float4*>(W)[row * 256 + kq]
        : reinterpret_cast<const float4*>(R)[row * 512 + (kq - 256)];
    const long long o = (long long)(gate * DH + row) * KTOT + (long long)kq * 4;
    *reinterpret_cast<__half2*>(dst + o)     = __half2(__float2half_rn(v.x), __float2half_rn(v.y));
    *reinterpret_cast<__half2*>(dst + o + 2) = __half2(__float2half_rn(v.z), __float2half_rn(v.w));
}

// ---------------- fused GEMM (HMMA) + sLSTM epilogue ----------------
__global__ void __launch_bounds__(256, 2)
slstm_hmma_kernel(const __half* __restrict__ Ahi, const __half* __restrict__ Alo,
                  const __half* __restrict__ B,
                  const float* __restrict__ c_prev, const float* __restrict__ n_prev,
                  const float* __restrict__ bz, const float* __restrict__ bi,
                  const float* __restrict__ bf, const float* __restrict__ bo,
                  float* __restrict__ h_out)
{
    extern __shared__ char smem[];
    const uint32_t sbase = smem_u32(smem);

    const int tid  = threadIdx.x;
    const int lane = tid & 31;
    const int wid  = tid >> 5;           // 0..7
    const int gate = wid & 3;
    const int m0   = (wid >> 2) * 32;    // warp rows [m0, m0+32)

    const int row0 = blockIdx.x * BM;    // row-block fast
    const int col0 = blockIdx.y * BN;

    // ---- stage loader: 12 cp.async(16B) per thread (256 threads, 48 KB stage) ----
    const int lr = tid >> 3;             // 0..31
    const int ls = tid & 7;

    auto load_stage = [&](int s, int k0) {
        const uint32_t st = sbase + s * STAGE;
#pragma unroll
        for (int it = 0; it < 2; ++it) {             // A: 64 rows, hi+lo
            const int r = lr + it * 32;
            const uint32_t off = SW128((uint32_t)(r * 128 + ls * 16));
            const size_t gi = (size_t)(row0 + r) * KTOT + k0 + ls * 8;
            cp_async16(st + OFF_AHI + off, Ahi + gi);
            cp_async16(st + OFF_ALO + off, Alo + gi);
        }
#pragma unroll
        for (int g = 0; g < 4; ++g) {                // B: 64 rows per gate
#pragma unroll
            for (int it = 0; it < 2; ++it) {
                const int r = lr + it * 32;
                const uint32_t off = SW128((uint32_t)(r * 128 + ls * 16));
                const size_t gi = (size_t)(g * DH + col0 + r) * KTOT + k0 + ls * 8;
                cp_async16(st + OFF_B + g * B_TILE + off, B + gi);
            }
        }
        CP_COMMIT();
    };

    // ---- per-lane ldmatrix address components (validated R3-R5) ----
    const uint32_t xr     = (uint32_t)(lane & 7) << 4;
    const uint32_t a_row  = (uint32_t)(lane & 15);
    const uint32_t a_sel  = (lane & 16) ? 16u : 0u;
    const uint32_t b_rowl = (uint32_t)((lane & 7) + ((lane & 16) ? 8 : 0));
    const uint32_t b_sel  = (lane & 8) ? 16u : 0u;

    float acc[2][8][4];
#pragma unroll
    for (int mt = 0; mt < 2; ++mt)
#pragma unroll
        for (int nt = 0; nt < 8; ++nt)
#pragma unroll
            for (int e = 0; e < 4; ++e) acc[mt][nt][e] = 0.0f;

    load_stage(0, 0);

#pragma unroll 1
    for (int c = 0; c < NCH; ++c) {
        if (c + 1 < NCH) { load_stage((c + 1) & 1, (c + 1) * BK); CP_WAIT(1); }
        else             { CP_WAIT(0); }
        __syncthreads();

        const uint32_t st   = sbase + (c & 1) * STAGE;
        const uint32_t ahiB = st + OFF_AHI;
        const uint32_t aloB = st + OFF_ALO;
        const uint32_t bB   = st + OFF_B + gate * B_TILE;

#pragma unroll
        for (int j = 0; j < 4; ++j) {                // k16 steps within BK=64
            const uint32_t akb = ((uint32_t)(j * 32) + a_sel) ^ xr;
            const uint32_t bkb = ((uint32_t)(j * 32) + b_sel) ^ xr;

            uint32_t bh[4][4];
#pragma unroll
            for (int np = 0; np < 4; ++np) {
                const uint32_t rbyte = (np * 16 + b_rowl) * 128;
                ldm_x4(bh[np], bB + rbyte + bkb);
            }
#pragma unroll
            for (int mt = 0; mt < 2; ++mt) {
                uint32_t ah[4], al[4];
                const uint32_t rbyte = (m0 + mt * 16 + a_row) * 128;
                ldm_x4(ah, ahiB + rbyte + akb);
                ldm_x4(al, aloB + rbyte + akb);
#pragma unroll
                for (int np = 0; np < 4; ++np)
#pragma unroll
                    for (int s = 0; s < 2; ++s) {
                        float* d = acc[mt][np * 2 + s];
                        mma_f16(d, ah, &bh[np][2 * s]);
                        mma_f16(d, al, &bh[np][2 * s]);
                    }
            }
        }
        __syncthreads();
    }

    // ---- exchange gates through smem, then fused sLSTM epilogue ----
    float* pre = reinterpret_cast<float*>(smem);   // [4][64][PRE_LD]
    float* pg = pre + (size_t)gate * BM * PRE_LD;
#pragma unroll
    for (int mt = 0; mt < 2; ++mt) {
        const int r = m0 + mt * 16 + (lane >> 2);
#pragma unroll
        for (int nt = 0; nt < 8; ++nt) {
            const int cc = nt * 8 + (lane & 3) * 2;
            pg[(size_t)r * PRE_LD + cc]           = acc[mt][nt][0];
            pg[(size_t)r * PRE_LD + cc + 1]       = acc[mt][nt][1];
            pg[(size_t)(r + 8) * PRE_LD + cc]     = acc[mt][nt][2];
            pg[(size_t)(r + 8) * PRE_LD + cc + 1] = acc[mt][nt][3];
        }
    }
    __syncthreads();

    {
        const int r     = tid >> 2;            // 0..63
        const int cbase = (tid & 3) * 16;      // 16 cols per thread
        const size_t gbase = (size_t)(row0 + r) * DH + col0 + cbase;
        const int    col   = col0 + cbase;

#pragma unroll
        for (int q = 0; q < 4; ++q) {
            const int cq = cbase + q * 4;
            const float4 bz4 = *reinterpret_cast<const float4*>(bz + col + q * 4);
            const float4 bi4 = *reinterpret_cast<const float4*>(bi + col + q * 4);
            const float4 bf4 = *reinterpret_cast<const float4*>(bf + col + q * 4);
            const float4 bo4 = *reinterpret_cast<const float4*>(bo + col + q * 4);
            const float4 c4  = *reinterpret_cast<const float4*>(c_prev + gbase + q * 4);
            const float4 n4  = *reinterpret_cast<const float4*>(n_prev + gbase + q * 4);
            const float bzr[4] = {bz4.x, bz4.y, bz4.z, bz4.w};
            const float bir[4] = {bi4.x, bi4.y, bi4.z, bi4.w};
            const float bfr[4] = {bf4.x, bf4.y, bf4.z, bf4.w};
            const float bor[4] = {bo4.x, bo4.y, bo4.z, bo4.w};
            const float cpr[4] = {c4.x, c4.y, c4.z, c4.w};
            const float npr[4] = {n4.x, n4.y, n4.z, n4.w};
            float hv[4];
#pragma unroll
            for (int e = 0; e < 4; ++e) {
                const size_t pix = (size_t)r * PRE_LD + cq + e;
                const float az = pre[0 * BM * PRE_LD + pix] + bzr[e];
                const float ai = pre[1 * BM * PRE_LD + pix] + bir[e];
                const float af = pre[2 * BM * PRE_LD + pix] + bfr[e];
                const float ao = pre[3 * BM * PRE_LD + pix] + bor[e];
                const float z  = tanhf(az);
                const float iv = expf(ai);
                const float fv = expf(af);
                const float ov = 1.0f / (1.0f + expf(-ao));
                const float cn = fv * cpr[e] + iv * z;
                const float nn = fv * npr[e] + iv;
                hv[e] = ov * (cn / nn);
            }
            *reinterpret_cast<float4*>(h_out + gbase + q * 4) =
                make_float4(hv[0], hv[1], hv[2], hv[3]);
        }
    }
}

// ---------------- launch ----------------
extern "C" void kernel_launch(void* const* d_in, const int* in_sizes, int n_in,
                              void* d_out, int out_size)
{
    const float* x      = (const float*)d_in[0];
    const float* h_prev = (const float*)d_in[1];
    const float* c_prev = (const float*)d_in[2];
    const float* n_prev = (const float*)d_in[3];
    const float* W0 = (const float*)d_in[4];
    const float* W1 = (const float*)d_in[5];
    const float* W2 = (const float*)d_in[6];
    const float* W3 = (const float*)d_in[7];
    const float* bz = (const float*)d_in[8];
    const float* bi = (const float*)d_in[9];
    const float* bf = (const float*)d_in[10];
    const float* bo = (const float*)d_in[11];
    const float* R0 = (const float*)d_in[12];
    const float* R1 = (const float*)d_in[13];
    const float* R2 = (const float*)d_in[14];
    const float* R3 = (const float*)d_in[15];
    float* out = (float*)d_out;

    __half *pAhi, *pAlo, *pB;
    cudaGetSymbolAddress((void**)&pAhi, g_Ahi);
    cudaGetSymbolAddress((void**)&pAlo, g_Alo);
    cudaGetSymbolAddress((void**)&pB,   g_B);

    cvtA_kernel<<<(BATCH * 768) / 256, 256>>>(x, h_prev, pAhi, pAlo);
    cvtB_kernel<<<(4 * DH * 768) / 256, 256>>>(W0, W1, W2, W3, R0, R1, R2, R3, pB);

    cudaFuncSetAttribute(slstm_hmma_kernel, cudaFuncAttributeMaxDynamicSharedMemorySize, SMEM_REQ);
    dim3 grid(BATCH / BM, DH / BN);   // (64, 32)
    slstm_hmma_kernel<<<grid, 256, SMEM_REQ>>>(pAhi, pAlo, pB,
                                               c_prev, n_prev, bz, bi, bf, bo, out);
}

// round 7
// speedup vs baseline: 8.5150x; 1.7787x over previous
#include <cuda_runtime.h>
#include <cuda_fp16.h>
#include <cstdint>
#include <math.h>

// sLSTM cell: plain-fp16 GEMM via mma.sync (HMMA, fp32 accum) + fused epilogue.
// R7: drop A lo-term (measured error budget allows it) -> HMMA work halves.
// pre[b, g*2048+n] = sum_k A[b,k]*Bg[n,k];  A=[x|h_prev] (K=3072), Bg=[Wg|Rg], both fp16.

namespace {
constexpr int BATCH = 4096;
constexpr int DH    = 2048;
constexpr int KTOT  = 3072;

constexpr int BM = 64;
constexpr int BN = 64;               // cols per gate
constexpr int BK = 64;               // 128B rows in fp16
constexpr int NCH = KTOT / BK;       // 48

constexpr int A_TILE = BM * BK * 2;              // 8192 B
constexpr int B_TILE = BN * BK * 2;              // 8192 B per gate
constexpr int OFF_A  = 0;
constexpr int OFF_B  = A_TILE;                   // 8192 (+ g*8192)
constexpr int STAGE  = OFF_B + 4 * B_TILE;       // 40960
constexpr int PRE_LD = 68;
constexpr int SMEM_REQ = 2 * STAGE;              // 81920 (>= 4*64*68*4 = 69632)
} // namespace

__device__ __half g_A[(size_t)BATCH * KTOT];
__device__ __half g_B[(size_t)4 * DH * KTOT];

__device__ __forceinline__ uint32_t smem_u32(const void* p) {
    uint32_t a;
    asm("{ .reg .u64 t; cvta.to.shared.u64 t, %1; cvt.u32.u64 %0, t; }" : "=r"(a) : "l"(p));
    return a;
}
__device__ __forceinline__ void cp_async16(uint32_t dst, const void* src) {
    asm volatile("cp.async.cg.shared.global [%0], [%1], 16;" :: "r"(dst), "l"(src) : "memory");
}
#define CP_COMMIT()  asm volatile("cp.async.commit_group;" ::: "memory")
#define CP_WAIT(n)   asm volatile("cp.async.wait_group %0;" :: "n"(n) : "memory")

__device__ __forceinline__ void ldm_x4(uint32_t* r, uint32_t addr) {
    asm volatile("ldmatrix.sync.aligned.m8n8.x4.shared.b16 {%0,%1,%2,%3}, [%4];"
                 : "=r"(r[0]), "=r"(r[1]), "=r"(r[2]), "=r"(r[3]) : "r"(addr));
}
__device__ __forceinline__ void mma_f16(float* d, const uint32_t* a, const uint32_t* b) {
    asm volatile("mma.sync.aligned.m16n8k16.row.col.f32.f16.f16.f32 "
                 "{%0,%1,%2,%3}, {%4,%5,%6,%7}, {%8,%9}, {%0,%1,%2,%3};"
                 : "+f"(d[0]), "+f"(d[1]), "+f"(d[2]), "+f"(d[3])
                 : "r"(a[0]), "r"(a[1]), "r"(a[2]), "r"(a[3]), "r"(b[0]), "r"(b[1]));
}
#define SW128(off) ((off) ^ (((off) >> 3) & 0x70))

// ---------------- prepass A: x|h_prev -> fp16 (one launch) ----------------
__global__ void __launch_bounds__(256)
cvtA_kernel(const float* __restrict__ x, const float* __restrict__ h_prev,
            __half* __restrict__ dst)
{
    const int i   = blockIdx.x * blockDim.x + threadIdx.x;   // 0 .. 4096*768-1
    const int row = i / 768;
    const int kq  = i - row * 768;
    const float4 v = (kq < 256)
        ? reinterpret_cast<const float4*>(x)[row * 256 + kq]
        : reinterpret_cast<const float4*>(h_prev)[row * 512 + (kq - 256)];
    const long long o = (long long)row * KTOT + (long long)kq * 4;
    *reinterpret_cast<__half2*>(dst + o)     = __half2(__float2half_rn(v.x), __float2half_rn(v.y));
    *reinterpret_cast<__half2*>(dst + o + 2) = __half2(__float2half_rn(v.z), __float2half_rn(v.w));
}

// ---------------- prepass B: all 4 gates W|R -> fp16 (one launch) ----------------
__global__ void __launch_bounds__(256)
cvtB_kernel(const float* __restrict__ W0, const float* __restrict__ W1,
            const float* __restrict__ W2, const float* __restrict__ W3,
            const float* __restrict__ R0, const float* __restrict__ R1,
            const float* __restrict__ R2, const float* __restrict__ R3,
            __half* __restrict__ dst)
{
    const int i    = blockIdx.x * blockDim.x + threadIdx.x;  // 0 .. 4*2048*768-1
    const int gate = i / (DH * 768);
    const int j    = i - gate * (DH * 768);
    const int row  = j / 768;
    const int kq   = j - row * 768;
    const float* W = (gate < 2) ? (gate == 0 ? W0 : W1) : (gate == 2 ? W2 : W3);
    const float* R = (gate < 2) ? (gate == 0 ? R0 : R1) : (gate == 2 ? R2 : R3);
    const float4 v = (kq < 256)
        ? reinterpret_cast<const float4*>(W)[row * 256 + kq]
        : reinterpret_cast<const float4*>(R)[row * 512 + (kq - 256)];
    const long long o = (long long)(gate * DH + row) * KTOT + (long long)kq * 4;
    *reinterpret_cast<__half2*>(dst + o)     = __half2(__float2half_rn(v.x), __float2half_rn(v.y));
    *reinterpret_cast<__half2*>(dst + o + 2) = __half2(__float2half_rn(v.z), __float2half_rn(v.w));
}

// ---------------- fused GEMM (HMMA) + sLSTM epilogue ----------------
__global__ void __launch_bounds__(256, 2)
slstm_hmma_kernel(const __half* __restrict__ A, const __half* __restrict__ B,
                  const float* __restrict__ c_prev, const float* __restrict__ n_prev,
                  const float* __restrict__ bz, const float* __restrict__ bi,
                  const float* __restrict__ bf, const float* __restrict__ bo,
                  float* __restrict__ h_out)
{
    extern __shared__ char smem[];
    const uint32_t sbase = smem_u32(smem);

    const int tid  = threadIdx.x;
    const int lane = tid & 31;
    const int wid  = tid >> 5;           // 0..7
    const int gate = wid & 3;
    const int m0   = (wid >> 2) * 32;    // warp rows [m0, m0+32)

    const int row0 = blockIdx.x * BM;    // row-block fast
    const int col0 = blockIdx.y * BN;

    // ---- stage loader: 10 cp.async(16B) per thread ----
    const int lr = tid >> 3;             // 0..31
    const int ls = tid & 7;

    auto load_stage = [&](int s, int k0) {
        const uint32_t st = sbase + s * STAGE;
#pragma unroll
        for (int it = 0; it < 2; ++it) {             // A: 64 rows
            const int r = lr + it * 32;
            const uint32_t off = SW128((uint32_t)(r * 128 + ls * 16));
            const size_t gi = (size_t)(row0 + r) * KTOT + k0 + ls * 8;
            cp_async16(st + OFF_A + off, A + gi);
        }
#pragma unroll
        for (int g = 0; g < 4; ++g) {                // B: 64 rows per gate
#pragma unroll
            for (int it = 0; it < 2; ++it) {
                const int r = lr + it * 32;
                const uint32_t off = SW128((uint32_t)(r * 128 + ls * 16));
                const size_t gi = (size_t)(g * DH + col0 + r) * KTOT + k0 + ls * 8;
                cp_async16(st + OFF_B + g * B_TILE + off, B + gi);
            }
        }
        CP_COMMIT();
    };

    // ---- per-lane ldmatrix address components (validated R3-R6) ----
    const uint32_t xr     = (uint32_t)(lane & 7) << 4;
    const uint32_t a_row  = (uint32_t)(lane & 15);
    const uint32_t a_sel  = (lane & 16) ? 16u : 0u;
    const uint32_t b_rowl = (uint32_t)((lane & 7) + ((lane & 16) ? 8 : 0));
    const uint32_t b_sel  = (lane & 8) ? 16u : 0u;

    float acc[2][8][4];
#pragma unroll
    for (int mt = 0; mt < 2; ++mt)
#pragma unroll
        for (int nt = 0; nt < 8; ++nt)
#pragma unroll
            for (int e = 0; e < 4; ++e) acc[mt][nt][e] = 0.0f;

    load_stage(0, 0);

#pragma unroll 1
    for (int c = 0; c < NCH; ++c) {
        if (c + 1 < NCH) { load_stage((c + 1) & 1, (c + 1) * BK); CP_WAIT(1); }
        else             { CP_WAIT(0); }
        __syncthreads();

        const uint32_t st  = sbase + (c & 1) * STAGE;
        const uint32_t aB  = st + OFF_A;
        const uint32_t bB  = st + OFF_B + gate * B_TILE;

#pragma unroll
        for (int j = 0; j < 4; ++j) {                // k16 steps within BK=64
            const uint32_t akb = ((uint32_t)(j * 32) + a_sel) ^ xr;
            const uint32_t bkb = ((uint32_t)(j * 32) + b_sel) ^ xr;

            uint32_t bh[4][4];
#pragma unroll
            for (int np = 0; np < 4; ++np) {
                const uint32_t rbyte = (np * 16 + b_rowl) * 128;
                ldm_x4(bh[np], bB + rbyte + bkb);
            }
#pragma unroll
            for (int mt = 0; mt < 2; ++mt) {
                uint32_t ah[4];
                const uint32_t rbyte = (m0 + mt * 16 + a_row) * 128;
                ldm_x4(ah, aB + rbyte + akb);
#pragma unroll
                for (int np = 0; np < 4; ++np)
#pragma unroll
                    for (int s = 0; s < 2; ++s)
                        mma_f16(acc[mt][np * 2 + s], ah, &bh[np][2 * s]);
            }
        }
        __syncthreads();
    }

    // ---- exchange gates through smem, then fused sLSTM epilogue ----
    float* pre = reinterpret_cast<float*>(smem);   // [4][64][PRE_LD]
    float* pg = pre + (size_t)gate * BM * PRE_LD;
#pragma unroll
    for (int mt = 0; mt < 2; ++mt) {
        const int r = m0 + mt * 16 + (lane >> 2);
#pragma unroll
        for (int nt = 0; nt < 8; ++nt) {
            const int cc = nt * 8 + (lane & 3) * 2;
            pg[(size_t)r * PRE_LD + cc]           = acc[mt][nt][0];
            pg[(size_t)r * PRE_LD + cc + 1]       = acc[mt][nt][1];
            pg[(size_t)(r + 8) * PRE_LD + cc]     = acc[mt][nt][2];
            pg[(size_t)(r + 8) * PRE_LD + cc + 1] = acc[mt][nt][3];
        }
    }
    __syncthreads();

    {
        const int r     = tid >> 2;            // 0..63
        const int cbase = (tid & 3) * 16;      // 16 cols per thread
        const size_t gbase = (size_t)(row0 + r) * DH + col0 + cbase;
        const int    col   = col0 + cbase;

#pragma unroll
        for (int q = 0; q < 4; ++q) {
            const int cq = cbase + q * 4;
            const float4 bz4 = *reinterpret_cast<const float4*>(bz + col + q * 4);
            const float4 bi4 = *reinterpret_cast<const float4*>(bi + col + q * 4);
            const float4 bf4 = *reinterpret_cast<const float4*>(bf + col + q * 4);
            const float4 bo4 = *reinterpret_cast<const float4*>(bo + col + q * 4);
            const float4 c4  = *reinterpret_cast<const float4*>(c_prev + gbase + q * 4);
            const float4 n4  = *reinterpret_cast<const float4*>(n_prev + gbase + q * 4);
            const float bzr[4] = {bz4.x, bz4.y, bz4.z, bz4.w};
            const float bir[4] = {bi4.x, bi4.y, bi4.z, bi4.w};
            const float bfr[4] = {bf4.x, bf4.y, bf4.z, bf4.w};
            const float bor[4] = {bo4.x, bo4.y, bo4.z, bo4.w};
            const float cpr[4] = {c4.x, c4.y, c4.z, c4.w};
            const float npr[4] = {n4.x, n4.y, n4.z, n4.w};
            float hv[4];
#pragma unroll
            for (int e = 0; e < 4; ++e) {
                const size_t pix = (size_t)r * PRE_LD + cq + e;
                const float az = pre[0 * BM * PRE_LD + pix] + bzr[e];
                const float ai = pre[1 * BM * PRE_LD + pix] + bir[e];
                const float af = pre[2 * BM * PRE_LD + pix] + bfr[e];
                const float ao = pre[3 * BM * PRE_LD + pix] + bor[e];
                const float z  = tanhf(az);
                const float iv = expf(ai);
                const float fv = expf(af);
                const float ov = 1.0f / (1.0f + expf(-ao));
                const float cn = fv * cpr[e] + iv * z;
                const float nn = fv * npr[e] + iv;
                hv[e] = ov * (cn / nn);
            }
            *reinterpret_cast<float4*>(h_out + gbase + q * 4) =
                make_float4(hv[0], hv[1], hv[2], hv[3]);
        }
    }
}

// ---------------- launch ----------------
extern "C" void kernel_launch(void* const* d_in, const int* in_sizes, int n_in,
                              void* d_out, int out_size)
{
    const float* x      = (const float*)d_in[0];
    const float* h_prev = (const float*)d_in[1];
    const float* c_prev = (const float*)d_in[2];
    const float* n_prev = (const float*)d_in[3];
    const float* W0 = (const float*)d_in[4];
    const float* W1 = (const float*)d_in[5];
    const float* W2 = (const float*)d_in[6];
    const float* W3 = (const float*)d_in[7];
    const float* bz = (const float*)d_in[8];
    const float* bi = (const float*)d_in[9];
    const float* bf = (const float*)d_in[10];
    const float* bo = (const float*)d_in[11];
    const float* R0 = (const float*)d_in[12];
    const float* R1 = (const float*)d_in[13];
    const float* R2 = (const float*)d_in[14];
    const float* R3 = (const float*)d_in[15];
    float* out = (float*)d_out;

    __half *pA, *pB;
    cudaGetSymbolAddress((void**)&pA, g_A);
    cudaGetSymbolAddress((void**)&pB, g_B);

    cvtA_kernel<<<(BATCH * 768) / 256, 256>>>(x, h_prev, pA);
    cvtB_kernel<<<(4 * DH * 768) / 256, 256>>>(W0, W1, W2, W3, R0, R1, R2, R3, pB);

    cudaFuncSetAttribute(slstm_hmma_kernel, cudaFuncAttributeMaxDynamicSharedMemorySize, SMEM_REQ);
    dim3 grid(BATCH / BM, DH / BN);   // (64, 32)
    slstm_hmma_kernel<<<grid, 256, SMEM_REQ>>>(pA, pB,
                                               c_prev, n_prev, bz, bi, bf, bo, out);
}

// round 8
// speedup vs baseline: 8.6245x; 1.0129x over previous
#include <cuda_runtime.h>
#include <cuda_fp16.h>
#include <cstdint>
#include <math.h>

// sLSTM cell: plain-fp16 GEMM via mma.sync (HMMA, fp32 accum) + fused epilogue.
// R8: wider prepass (8 floats/thread, uint4 stores); epilogue with explicit
// approx-PTX transcendentals and folded division:
//   h = (r*c_prev + z) * rcp((r*n_prev + 1)*(1+exp(-ao))),  r = exp(af-ai).

namespace {
constexpr int BATCH = 4096;
constexpr int DH    = 2048;
constexpr int KTOT  = 3072;

constexpr int BM = 64;
constexpr int BN = 64;               // cols per gate
constexpr int BK = 64;               // 128B rows in fp16
constexpr int NCH = KTOT / BK;       // 48

constexpr int A_TILE = BM * BK * 2;              // 8192 B
constexpr int B_TILE = BN * BK * 2;              // 8192 B per gate
constexpr int OFF_A  = 0;
constexpr int OFF_B  = A_TILE;                   // 8192 (+ g*8192)
constexpr int STAGE  = OFF_B + 4 * B_TILE;       // 40960
constexpr int PRE_LD = 68;
constexpr int SMEM_REQ = 2 * STAGE;              // 81920 (>= 4*64*68*4 = 69632)

constexpr float LOG2E = 1.4426950408889634f;
} // namespace

__device__ __half g_A[(size_t)BATCH * KTOT];
__device__ __half g_B[(size_t)4 * DH * KTOT];

__device__ __forceinline__ uint32_t smem_u32(const void* p) {
    uint32_t a;
    asm("{ .reg .u64 t; cvta.to.shared.u64 t, %1; cvt.u32.u64 %0, t; }" : "=r"(a) : "l"(p));
    return a;
}
__device__ __forceinline__ void cp_async16(uint32_t dst, const void* src) {
    asm volatile("cp.async.cg.shared.global [%0], [%1], 16;" :: "r"(dst), "l"(src) : "memory");
}
#define CP_COMMIT()  asm volatile("cp.async.commit_group;" ::: "memory")
#define CP_WAIT(n)   asm volatile("cp.async.wait_group %0;" :: "n"(n) : "memory")

__device__ __forceinline__ void ldm_x4(uint32_t* r, uint32_t addr) {
    asm volatile("ldmatrix.sync.aligned.m8n8.x4.shared.b16 {%0,%1,%2,%3}, [%4];"
                 : "=r"(r[0]), "=r"(r[1]), "=r"(r[2]), "=r"(r[3]) : "r"(addr));
}
__device__ __forceinline__ void mma_f16(float* d, const uint32_t* a, const uint32_t* b) {
    asm volatile("mma.sync.aligned.m16n8k16.row.col.f32.f16.f16.f32 "
                 "{%0,%1,%2,%3}, {%4,%5,%6,%7}, {%8,%9}, {%0,%1,%2,%3};"
                 : "+f"(d[0]), "+f"(d[1]), "+f"(d[2]), "+f"(d[3])
                 : "r"(a[0]), "r"(a[1]), "r"(a[2]), "r"(a[3]), "r"(b[0]), "r"(b[1]));
}
__device__ __forceinline__ float ex2f(float x) {
    float y; asm("ex2.approx.f32 %0, %1;" : "=f"(y) : "f"(x)); return y;
}
__device__ __forceinline__ float rcpf(float x) {
    float y; asm("rcp.approx.f32 %0, %1;" : "=f"(y) : "f"(x)); return y;
}
#define SW128(off) ((off) ^ (((off) >> 3) & 0x70))

// ---- fp32x8 -> fp16x8 packed as uint4 ----
__device__ __forceinline__ uint4 pack8(const float4 a, const float4 b) {
    __half2 h0(__float2half_rn(a.x), __float2half_rn(a.y));
    __half2 h1(__float2half_rn(a.z), __float2half_rn(a.w));
    __half2 h2(__float2half_rn(b.x), __float2half_rn(b.y));
    __half2 h3(__float2half_rn(b.z), __float2half_rn(b.w));
    uint4 u;
    u.x = *reinterpret_cast<uint32_t*>(&h0);
    u.y = *reinterpret_cast<uint32_t*>(&h1);
    u.z = *reinterpret_cast<uint32_t*>(&h2);
    u.w = *reinterpret_cast<uint32_t*>(&h3);
    return u;
}

// ---------------- prepass A: x|h_prev -> fp16 (8 floats / thread) ----------------
__global__ void __launch_bounds__(256)
cvtA_kernel(const float* __restrict__ x, const float* __restrict__ h_prev,
            __half* __restrict__ dst)
{
    const int i   = blockIdx.x * blockDim.x + threadIdx.x;   // 0 .. 4096*384-1
    const int row = i / 384;
    const int sg  = i - row * 384;        // 8-float segment within K=3072
    float4 va, vb;
    if (sg < 128) {
        const float4* p = reinterpret_cast<const float4*>(x) + row * 256 + sg * 2;
        va = p[0]; vb = p[1];
    } else {
        const float4* p = reinterpret_cast<const float4*>(h_prev) + row * 512 + (sg - 128) * 2;
        va = p[0]; vb = p[1];
    }
    reinterpret_cast<uint4*>(dst + (size_t)row * KTOT)[sg] = pack8(va, vb);
}

// ---------------- prepass B: all 4 gates W|R -> fp16 (8 floats / thread) ----------------
__global__ void __launch_bounds__(256)
cvtB_kernel(const float* __restrict__ W0, const float* __restrict__ W1,
            const float* __restrict__ W2, const float* __restrict__ W3,
            const float* __restrict__ R0, const float* __restrict__ R1,
            const float* __restrict__ R2, const float* __restrict__ R3,
            __half* __restrict__ dst)
{
    const int i    = blockIdx.x * blockDim.x + threadIdx.x;  // 0 .. 4*2048*384-1
    const int gate = i / (DH * 384);
    const int j    = i - gate * (DH * 384);
    const int row  = j / 384;
    const int sg   = j - row * 384;
    const float* W = (gate < 2) ? (gate == 0 ? W0 : W1) : (gate == 2 ? W2 : W3);
    const float* R = (gate < 2) ? (gate == 0 ? R0 : R1) : (gate == 2 ? R2 : R3);
    float4 va, vb;
    if (sg < 128) {
        const float4* p = reinterpret_cast<const float4*>(W) + row * 256 + sg * 2;
        va = p[0]; vb = p[1];
    } else {
        const float4* p = reinterpret_cast<const float4*>(R) + row * 512 + (sg - 128) * 2;
        va = p[0]; vb = p[1];
    }
    reinterpret_cast<uint4*>(dst + (size_t)(gate * DH + row) * KTOT)[sg] = pack8(va, vb);
}

// ---------------- fused GEMM (HMMA) + sLSTM epilogue ----------------
__global__ void __launch_bounds__(256, 2)
slstm_hmma_kernel(const __half* __restrict__ A, const __half* __restrict__ B,
                  const float* __restrict__ c_prev, const float* __restrict__ n_prev,
                  const float* __restrict__ bz, const float* __restrict__ bi,
                  const float* __restrict__ bf, const float* __restrict__ bo,
                  float* __restrict__ h_out)
{
    extern __shared__ char smem[];
    const uint32_t sbase = smem_u32(smem);

    const int tid  = threadIdx.x;
    const int lane = tid & 31;
    const int wid  = tid >> 5;           // 0..7
    const int gate = wid & 3;
    const int m0   = (wid >> 2) * 32;    // warp rows [m0, m0+32)

    const int row0 = blockIdx.x * BM;    // row-block fast
    const int col0 = blockIdx.y * BN;

    // ---- stage loader: 10 cp.async(16B) per thread ----
    const int lr = tid >> 3;             // 0..31
    const int ls = tid & 7;

    auto load_stage = [&](int s, int k0) {
        const uint32_t st = sbase + s * STAGE;
#pragma unroll
        for (int it = 0; it < 2; ++it) {             // A: 64 rows
            const int r = lr + it * 32;
            const uint32_t off = SW128((uint32_t)(r * 128 + ls * 16));
            const size_t gi = (size_t)(row0 + r) * KTOT + k0 + ls * 8;
            cp_async16(st + OFF_A + off, A + gi);
        }
#pragma unroll
        for (int g = 0; g < 4; ++g) {                // B: 64 rows per gate
#pragma unroll
            for (int it = 0; it < 2; ++it) {
                const int r = lr + it * 32;
                const uint32_t off = SW128((uint32_t)(r * 128 + ls * 16));
                const size_t gi = (size_t)(g * DH + col0 + r) * KTOT + k0 + ls * 8;
                cp_async16(st + OFF_B + g * B_TILE + off, B + gi);
            }
        }
        CP_COMMIT();
    };

    // ---- per-lane ldmatrix address components (validated R3-R7) ----
    const uint32_t xr     = (uint32_t)(lane & 7) << 4;
    const uint32_t a_row  = (uint32_t)(lane & 15);
    const uint32_t a_sel  = (lane & 16) ? 16u : 0u;
    const uint32_t b_rowl = (uint32_t)((lane & 7) + ((lane & 16) ? 8 : 0));
    const uint32_t b_sel  = (lane & 8) ? 16u : 0u;

    float acc[2][8][4];
#pragma unroll
    for (int mt = 0; mt < 2; ++mt)
#pragma unroll
        for (int nt = 0; nt < 8; ++nt)
#pragma unroll
            for (int e = 0; e < 4; ++e) acc[mt][nt][e] = 0.0f;

    load_stage(0, 0);

#pragma unroll 1
    for (int c = 0; c < NCH; ++c) {
        if (c + 1 < NCH) { load_stage((c + 1) & 1, (c + 1) * BK); CP_WAIT(1); }
        else             { CP_WAIT(0); }
        __syncthreads();

        const uint32_t st  = sbase + (c & 1) * STAGE;
        const uint32_t aB  = st + OFF_A;
        const uint32_t bB  = st + OFF_B + gate * B_TILE;

#pragma unroll
        for (int j = 0; j < 4; ++j) {                // k16 steps within BK=64
            const uint32_t akb = ((uint32_t)(j * 32) + a_sel) ^ xr;
            const uint32_t bkb = ((uint32_t)(j * 32) + b_sel) ^ xr;

            uint32_t bh[4][4];
#pragma unroll
            for (int np = 0; np < 4; ++np) {
                const uint32_t rbyte = (np * 16 + b_rowl) * 128;
                ldm_x4(bh[np], bB + rbyte + bkb);
            }
#pragma unroll
            for (int mt = 0; mt < 2; ++mt) {
                uint32_t ah[4];
                const uint32_t rbyte = (m0 + mt * 16 + a_row) * 128;
                ldm_x4(ah, aB + rbyte + akb);
#pragma unroll
                for (int np = 0; np < 4; ++np)
#pragma unroll
                    for (int s = 0; s < 2; ++s)
                        mma_f16(acc[mt][np * 2 + s], ah, &bh[np][2 * s]);
            }
        }
        __syncthreads();
    }

    // ---- exchange gates through smem, then fused sLSTM epilogue ----
    float* pre = reinterpret_cast<float*>(smem);   // [4][64][PRE_LD]
    float* pg = pre + (size_t)gate * BM * PRE_LD;
#pragma unroll
    for (int mt = 0; mt < 2; ++mt) {
        const int r = m0 + mt * 16 + (lane >> 2);
#pragma unroll
        for (int nt = 0; nt < 8; ++nt) {
            const int cc = nt * 8 + (lane & 3) * 2;
            pg[(size_t)r * PRE_LD + cc]           = acc[mt][nt][0];
            pg[(size_t)r * PRE_LD + cc + 1]       = acc[mt][nt][1];
            pg[(size_t)(r + 8) * PRE_LD + cc]     = acc[mt][nt][2];
            pg[(size_t)(r + 8) * PRE_LD + cc + 1] = acc[mt][nt][3];
        }
    }
    __syncthreads();

    {
        const int r     = tid >> 2;            // 0..63
        const int cbase = (tid & 3) * 16;      // 16 cols per thread
        const size_t gbase = (size_t)(row0 + r) * DH + col0 + cbase;
        const int    col   = col0 + cbase;

#pragma unroll
        for (int q = 0; q < 4; ++q) {
            const int cq = cbase + q * 4;
            const float4 bz4 = *reinterpret_cast<const float4*>(bz + col + q * 4);
            const float4 bi4 = *reinterpret_cast<const float4*>(bi + col + q * 4);
            const float4 bf4 = *reinterpret_cast<const float4*>(bf + col + q * 4);
            const float4 bo4 = *reinterpret_cast<const float4*>(bo + col + q * 4);
            const float4 c4  = *reinterpret_cast<const float4*>(c_prev + gbase + q * 4);
            const float4 n4  = *reinterpret_cast<const float4*>(n_prev + gbase + q * 4);
            const float bzr[4] = {bz4.x, bz4.y, bz4.z, bz4.w};
            const float bir[4] = {bi4.x, bi4.y, bi4.z, bi4.w};
            const float bfr[4] = {bf4.x, bf4.y, bf4.z, bf4.w};
            const float bor[4] = {bo4.x, bo4.y, bo4.z, bo4.w};
            const float cpr[4] = {c4.x, c4.y, c4.z, c4.w};
            const float npr[4] = {n4.x, n4.y, n4.z, n4.w};
            float hv[4];
#pragma unroll
            for (int e = 0; e < 4; ++e) {
                const size_t pix = (size_t)r * PRE_LD + cq + e;
                const float az = pre[0 * BM * PRE_LD + pix] + bzr[e];
                const float ai = pre[1 * BM * PRE_LD + pix] + bir[e];
                const float af = pre[2 * BM * PRE_LD + pix] + bfr[e];
                const float ao = pre[3 * BM * PRE_LD + pix] + bor[e];
                // z = tanh(az) = 1 - 2/(exp(2*az)+1)
                const float u  = ex2f(2.0f * LOG2E * az);
                const float z  = 1.0f - 2.0f * rcpf(u + 1.0f);
                // r = f/i = exp(af - ai); eo = exp(-ao)
                const float rv = ex2f(LOG2E * (af - ai));
                const float eo = ex2f(-LOG2E * ao);
                // h = o*(c/n) = (r*c_prev + z) / ((r*n_prev + 1)*(1+eo))
                const float num = fmaf(rv, cpr[e], z);
                const float den = fmaf(rv, npr[e], 1.0f) * (1.0f + eo);
                hv[e] = num * rcpf(den);
            }
            *reinterpret_cast<float4*>(h_out + gbase + q * 4) =
                make_float4(hv[0], hv[1], hv[2], hv[3]);
        }
    }
}

// ---------------- launch ----------------
extern "C" void kernel_launch(void* const* d_in, const int* in_sizes, int n_in,
                              void* d_out, int out_size)
{
    const float* x      = (const float*)d_in[0];
    const float* h_prev = (const float*)d_in[1];
    const float* c_prev = (const float*)d_in[2];
    const float* n_prev = (const float*)d_in[3];
    const float* W0 = (const float*)d_in[4];
    const float* W1 = (const float*)d_in[5];
    const float* W2 = (const float*)d_in[6];
    const float* W3 = (const float*)d_in[7];
    const float* bz = (const float*)d_in[8];
    const float* bi = (const float*)d_in[9];
    const float* bf = (const float*)d_in[10];
    const float* bo = (const float*)d_in[11];
    const float* R0 = (const float*)d_in[12];
    const float* R1 = (const float*)d_in[13];
    const float* R2 = (const float*)d_in[14];
    const float* R3 = (const float*)d_in[15];
    float* out = (float*)d_out;

    __half *pA, *pB;
    cudaGetSymbolAddress((void**)&pA, g_A);
    cudaGetSymbolAddress((void**)&pB, g_B);

    cvtA_kernel<<<(BATCH * 384) / 256, 256>>>(x, h_prev, pA);
    cvtB_kernel<<<(4 * DH * 384) / 256, 256>>>(W0, W1, W2, W3, R0, R1, R2, R3, pB);

    cudaFuncSetAttribute(slstm_hmma_kernel, cudaFuncAttributeMaxDynamicSharedMemorySize, SMEM_REQ);
    dim3 grid(BATCH / BM, DH / BN);   // (64, 32)
    slstm_hmma_kernel<<<grid, 256, SMEM_REQ>>>(pA, pB,
                                               c_prev, n_prev, bz, bi, bf, bo, out);
}